// round 13
// baseline (speedup 1.0000x reference)
#include <cuda_runtime.h>
#include <cuda_bf16.h>
#include <cstdint>

// Problem constants
#define BB 32
#define SS 256
#define TT 64
#define EE 256
#define HH 512
#define VV 32000
#define H3 1536

// GEMM tile config
#define GBM 128
#define GBN 128
#define GBK 64
#define GLDA 72                 // padded row (bf16 elems)
#define GBUF_B (GBM * GLDA * 2) // 18432 bytes (128-row stage buffer)
#define MM_SMEM (6 * GBUF_B)    // gi: 3 stages x (A+B) = 110592

// fc: 128x256 block, 64x64 warp tile, 256 thr, 3-stage
#define FCBN 256
#define FCBUF (FCBN * GLDA * 2)            // 36864
#define FC_SMEM3 (3 * GBUF_B + 3 * FCBUF)  // 165888

// K layouts (deduplicated): stored [hi | lo]
#define FCK 2048
#define GIX 512
#define FC_NC 48                // 3 segments x 16 chunks
#define GI_NC 12

#define NCTA 128
#define DEC_WSMEM 49152

// ---------------- scratch ----------------
__device__ float g_enc_gi[SS * H3 * BB];
__device__ float g_dec_gie[TT * H3 * BB];
__device__ float g_eo[SS * HH * BB];
__device__ float g_h0[HH * BB];          // never written -> stays zero
__device__ float g_hdec[2][HH * BB];
__device__ float g_ctx[HH * BB];
__device__ float g_scores[SS * BB];
__device__ float g_pred[(TT * BB) * (2 * HH)];
__device__ __nv_bfloat16 g_Wb[(size_t)VV * FCK];
__device__ __nv_bfloat16 g_Ab[(size_t)(TT * BB) * FCK];
__device__ __nv_bfloat16 g_Xe[(size_t)(SS * BB) * GIX];
__device__ __nv_bfloat16 g_Xd[(size_t)(TT * BB) * GIX];
__device__ __nv_bfloat16 g_We[(size_t)H3 * GIX];
__device__ __nv_bfloat16 g_Wd[(size_t)H3 * GIX];
__device__ unsigned g_bar_cnt;
__device__ unsigned g_bar_gen;

// ---------------- grid barrier (proven) ----------------
__device__ __forceinline__ void grid_sync(unsigned nb) {
    __syncthreads();
    if (threadIdx.x == 0) {
        __threadfence();
        volatile unsigned* genp = &g_bar_gen;
        unsigned gen = *genp;
        if (atomicAdd(&g_bar_cnt, 1u) == nb - 1u) {
            g_bar_cnt = 0;
            __threadfence();
            *genp = gen + 1u;
        } else {
            while (*genp == gen) { }
            __threadfence();
        }
    }
    __syncthreads();
}

__device__ __forceinline__ float sigm(float x) { return 1.0f / (1.0f + __expf(-x)); }

__device__ __forceinline__ uint32_t smem_u32(const void* p) {
    uint32_t a;
    asm("{ .reg .u64 t; cvta.to.shared.u64 t, %1; cvt.u32.u64 %0, t; }" : "=r"(a) : "l"(p));
    return a;
}
__device__ __forceinline__ void cpasync16(uint32_t dst, const void* src) {
    asm volatile("cp.async.cg.shared.global [%0], [%1], 16;" :: "r"(dst), "l"(src) : "memory");
}
#define LDSM4(r0, r1, r2, r3, addr) \
    asm volatile("ldmatrix.sync.aligned.m8n8.x4.shared.b16 {%0,%1,%2,%3}, [%4];" \
                 : "=r"(r0), "=r"(r1), "=r"(r2), "=r"(r3) : "r"(addr))
#define MMA16816(c, a, b0, b1) \
    asm volatile("mma.sync.aligned.m16n8k16.row.col.f32.bf16.bf16.f32 " \
                 "{%0,%1,%2,%3}, {%4,%5,%6,%7}, {%8,%9}, {%0,%1,%2,%3};" \
                 : "+f"((c)[0]), "+f"((c)[1]), "+f"((c)[2]), "+f"((c)[3]) \
                 : "r"((a)[0]), "r"((a)[1]), "r"((a)[2]), "r"((a)[3]), "r"(b0), "r"(b1))

__device__ __forceinline__ void split4(float4 v, __nv_bfloat162& hA, __nv_bfloat162& hB,
                                       __nv_bfloat162& lA, __nv_bfloat162& lB) {
    __nv_bfloat16 h0 = __float2bfloat16(v.x), h1 = __float2bfloat16(v.y);
    __nv_bfloat16 h2 = __float2bfloat16(v.z), h3 = __float2bfloat16(v.w);
    __nv_bfloat16 l0 = __float2bfloat16(v.x - __bfloat162float(h0));
    __nv_bfloat16 l1 = __float2bfloat16(v.y - __bfloat162float(h1));
    __nv_bfloat16 l2 = __float2bfloat16(v.z - __bfloat162float(h2));
    __nv_bfloat16 l3 = __float2bfloat16(v.w - __bfloat162float(h3));
    hA = {h0, h1}; hB = {h2, h3}; lA = {l0, l1}; lB = {l2, l3};
}

// ---------------- W split: g_Wb[n] = [hi | lo]
__global__ void convW(const float* __restrict__ W) {
    size_t i = (size_t)blockIdx.x * 1024 + threadIdx.x;
    float4 v = ((const float4*)W)[i];
    size_t n = i >> 8;
    size_t k4 = (i & 255) * 4;
    __nv_bfloat162 hA, hB, lA, lB;
    split4(v, hA, hB, lA, lB);
    __nv_bfloat16* dst = g_Wb + n * FCK;
    *(__nv_bfloat162*)(dst + k4) = hA;          *(__nv_bfloat162*)(dst + k4 + 2) = hB;
    *(__nv_bfloat162*)(dst + 1024 + k4) = lA;   *(__nv_bfloat162*)(dst + 1024 + k4 + 2) = lB;
}

// ---------------- pred split: g_Ab[m] = [hi | lo]
__global__ void convA() {
    size_t i = (size_t)blockIdx.x * 1024 + threadIdx.x;
    float4 v = ((const float4*)g_pred)[i];
    size_t m = i >> 8;
    size_t k4 = (i & 255) * 4;
    __nv_bfloat162 hA, hB, lA, lB;
    split4(v, hA, hB, lA, lB);
    __nv_bfloat16* dst = g_Ab + m * FCK;
    *(__nv_bfloat162*)(dst + k4) = hA;          *(__nv_bfloat162*)(dst + k4 + 2) = hB;
    *(__nv_bfloat162*)(dst + 1024 + k4) = lA;   *(__nv_bfloat162*)(dst + 1024 + k4 + 2) = lB;
}

// ---------------- gather embedding rows + split
__global__ void gatherX(const float* __restrict__ emb, const int* __restrict__ tok,
                        int L, int which) {
    __nv_bfloat16* X = which ? g_Xd : g_Xe;
    int m = blockIdx.x * 8 + (threadIdx.x >> 5);
    int lane = threadIdx.x & 31;
    int t = m >> 5, b = m & 31;
    int tv = tok[b * L + t];
    const float4* er = (const float4*)(emb + (size_t)tv * EE);
    __nv_bfloat16* dst = X + (size_t)m * GIX;
    #pragma unroll
    for (int q = 0; q < 2; q++) {
        float4 v = er[lane * 2 + q];
        int e = lane * 8 + q * 4;
        __nv_bfloat162 hA, hB, lA, lB;
        split4(v, hA, hB, lA, lB);
        *(__nv_bfloat162*)(dst + e) = hA;            *(__nv_bfloat162*)(dst + e + 2) = hB;
        *(__nv_bfloat162*)(dst + 256 + e) = lA;      *(__nv_bfloat162*)(dst + 256 + e + 2) = lB;
    }
}

// ---------------- split Wih rows (first 256 cols)
__global__ void splitWih(const float* __restrict__ W, int stride, int which) {
    __nv_bfloat16* out = which ? g_Wd : g_We;
    int j = blockIdx.x * 8 + (threadIdx.x >> 5);
    int lane = threadIdx.x & 31;
    const float4* wr = (const float4*)(W + (size_t)j * stride);
    __nv_bfloat16* dst = out + (size_t)j * GIX;
    #pragma unroll
    for (int q = 0; q < 2; q++) {
        float4 v = wr[lane * 2 + q];
        int e = lane * 8 + q * 4;
        __nv_bfloat162 hA, hB, lA, lB;
        split4(v, hA, hB, lA, lB);
        *(__nv_bfloat162*)(dst + e) = hA;            *(__nv_bfloat162*)(dst + e + 2) = hB;
        *(__nv_bfloat162*)(dst + 256 + e) = lA;      *(__nv_bfloat162*)(dst + 256 + e + 2) = lB;
    }
}

// ---------------- gi GEMM via HMMA (256 thr, 128x128, K eff 768)
__global__ void __launch_bounds__(256) gi_mma(const float* __restrict__ bih, int which) {
    extern __shared__ uint8_t dynsmem[];
    uint32_t sA = smem_u32(dynsmem);
    uint32_t sB = sA + 3 * GBUF_B;

    const __nv_bfloat16* A = which ? g_Xd : g_Xe;
    const __nv_bfloat16* Bm = which ? g_Wd : g_We;
    float* outg = which ? g_dec_gie : g_enc_gi;

    int tid = threadIdx.x;
    int wid = tid >> 5, lane = tid & 31;
    int wm = wid & 3, wn = wid >> 2;
    int m0 = blockIdx.x * GBM;
    int n0 = blockIdx.y * GBN;

    const char* Ag = (const char*)(A + (size_t)m0 * GIX);
    const char* Bg = (const char*)(Bm + (size_t)n0 * GIX);
    int lrow = tid >> 3, lu = tid & 7;

    auto load_chunk = [&](int kc, int st) {
        int seg = kc >> 2, c = kc & 3;
        size_t aoff = (size_t)(((seg == 2) ? 256 : 0) + c * 64) * 2;
        size_t boff = (size_t)(((seg == 1) ? 256 : 0) + c * 64) * 2;
        uint32_t sa = sA + st * GBUF_B;
        uint32_t sbm = sB + st * GBUF_B;
        #pragma unroll
        for (int it = 0; it < 4; it++) {
            int row = it * 32 + lrow;
            uint32_t doff = (uint32_t)(row * (GLDA * 2) + lu * 16);
            cpasync16(sa + doff, Ag + (size_t)row * (GIX * 2) + aoff + lu * 16);
            cpasync16(sbm + doff, Bg + (size_t)row * (GIX * 2) + boff + lu * 16);
        }
        asm volatile("cp.async.commit_group;" ::: "memory");
    };

    float acc[2][8][4];
    #pragma unroll
    for (int a = 0; a < 2; a++)
        #pragma unroll
        for (int b = 0; b < 8; b++)
            #pragma unroll
            for (int c = 0; c < 4; c++) acc[a][b][c] = 0.0f;

    uint32_t aBase = (uint32_t)(((wm * 32 + (lane & 15)) * GLDA + (lane >> 4) * 8) * 2);
    uint32_t bBase = (uint32_t)(((wn * 64 + (lane & 7) + ((lane >> 4) & 1) * 8) * GLDA
                                 + ((lane >> 3) & 1) * 8) * 2);

    load_chunk(0, 0);
    load_chunk(1, 1);
    for (int kc = 0; kc < GI_NC; kc++) {
        int st = kc % 3;
        if (kc == GI_NC - 1) { asm volatile("cp.async.wait_group 0;" ::: "memory"); }
        else                 { asm volatile("cp.async.wait_group 1;" ::: "memory"); }
        __syncthreads();
        if (kc + 2 < GI_NC) load_chunk(kc + 2, (kc + 2) % 3);
        uint32_t sa = sA + st * GBUF_B + aBase;
        uint32_t sbm = sB + st * GBUF_B + bBase;
        #pragma unroll
        for (int ks = 0; ks < 4; ks++) {
            uint32_t koff = (uint32_t)(ks * 16 * 2);
            uint32_t a0[4], a1[4];
            LDSM4(a0[0], a0[1], a0[2], a0[3], sa + koff);
            LDSM4(a1[0], a1[1], a1[2], a1[3], sa + 16 * GLDA * 2 + koff);
            uint32_t bf[16];
            #pragma unroll
            for (int nt = 0; nt < 4; nt++)
                LDSM4(bf[nt * 4 + 0], bf[nt * 4 + 1], bf[nt * 4 + 2], bf[nt * 4 + 3],
                      sbm + nt * 16 * GLDA * 2 + koff);
            #pragma unroll
            for (int j = 0; j < 8; j++) {
                int nt = j >> 1, hf = j & 1;
                MMA16816(acc[0][j], a0, bf[nt * 4 + hf * 2], bf[nt * 4 + hf * 2 + 1]);
                MMA16816(acc[1][j], a1, bf[nt * 4 + hf * 2], bf[nt * 4 + hf * 2 + 1]);
            }
        }
    }
    __syncthreads();

    #pragma unroll
    for (int mt = 0; mt < 2; mt++) {
        #pragma unroll
        for (int half = 0; half < 2; half++) {
            int m = m0 + wm * 32 + mt * 16 + (lane >> 2) + half * 8;
            int t = m >> 5, b = m & 31;
            float* obase = outg + (size_t)t * (H3 * BB) + b;
            #pragma unroll
            for (int j = 0; j < 8; j++) {
                int n = n0 + wn * 64 + j * 8 + (lane & 3) * 2;
                obase[(size_t)n * 32] = acc[mt][j][half * 2 + 0] + __ldg(bih + n);
                obase[(size_t)(n + 1) * 32] = acc[mt][j][half * 2 + 1] + __ldg(bih + n + 1);
            }
        }
    }
}

// ---------------- encoder scan (weights in SMEM, gi prefetched) ----------------
__global__ void __launch_bounds__(512) enc_scan(const float* __restrict__ Whh,
                                                const float* __restrict__ bhh) {
    int wid = threadIdx.x >> 5, lane = threadIdx.x & 31;
    int iLocal = wid & 3;
    int kq = wid >> 2;
    int i = blockIdx.x * 4 + iLocal;
    __shared__ float sW[16][3][128];
    __shared__ float ps[4][3][3][32];
    __shared__ float sgi[2][12][32];
    __shared__ float sbh[12];

    #pragma unroll
    for (int g = 0; g < 3; g++) {
        float4 w = *(const float4*)(Whh + ((size_t)g * HH + i) * HH + kq * 128 + lane * 4);
        *(float4*)&sW[wid][g][lane * 4] = w;
    }
    if (threadIdx.x < 12) {
        int g = threadIdx.x >> 2, il = threadIdx.x & 3;
        sbh[threadIdx.x] = bhh[g * HH + blockIdx.x * 4 + il];
    }

    auto prefetch_gi = [&](int t, int buf) {
        if (threadIdx.x < 96) {
            int row = threadIdx.x >> 3, u = threadIdx.x & 7;
            int g = row >> 2, il = row & 3;
            const float* src = g_enc_gi + (size_t)t * (H3 * BB)
                             + ((size_t)g * HH + blockIdx.x * 4 + il) * 32 + u * 4;
            cpasync16(smem_u32(&sgi[buf][row][u * 4]), src);
        }
        asm volatile("cp.async.commit_group;" ::: "memory");
    };
    prefetch_gi(0, 0);
    __syncthreads();

    for (int t = 0; t < SS; t++) {
        if (t + 1 < SS) prefetch_gi(t + 1, (t + 1) & 1);
        const float* hprev = t ? (g_eo + (t - 1) * (HH * BB)) : g_h0;
        const float* hp = hprev + kq * 128 * 32 + lane;
        float s0 = 0, s1 = 0, s2 = 0;
        #pragma unroll 8
        for (int q = 0; q < 32; q++) {
            float h0 = hp[q * 128 + 0];
            float h1 = hp[q * 128 + 32];
            float h2 = hp[q * 128 + 64];
            float h3 = hp[q * 128 + 96];
            float4 w0 = *(const float4*)&sW[wid][0][q * 4];
            float4 w1 = *(const float4*)&sW[wid][1][q * 4];
            float4 w2 = *(const float4*)&sW[wid][2][q * 4];
            s0 += w0.x * h0 + w0.y * h1 + w0.z * h2 + w0.w * h3;
            s1 += w1.x * h0 + w1.y * h1 + w1.z * h2 + w1.w * h3;
            s2 += w2.x * h0 + w2.y * h1 + w2.z * h2 + w2.w * h3;
        }
        if (kq > 0) {
            ps[iLocal][kq - 1][0][lane] = s0;
            ps[iLocal][kq - 1][1][lane] = s1;
            ps[iLocal][kq - 1][2][lane] = s2;
        }
        asm volatile("cp.async.wait_group 1;" ::: "memory");
        __syncthreads();
        if (wid < 4) {
            float rh = s0 + ps[wid][0][0][lane] + ps[wid][1][0][lane] + ps[wid][2][0][lane] + sbh[wid];
            float zh = s1 + ps[wid][0][1][lane] + ps[wid][1][1][lane] + ps[wid][2][1][lane] + sbh[4 + wid];
            float nh = s2 + ps[wid][0][2][lane] + ps[wid][1][2][lane] + ps[wid][2][2][lane] + sbh[8 + wid];
            float ir = sgi[t & 1][wid][lane];
            float iz = sgi[t & 1][4 + wid][lane];
            float in_ = sgi[t & 1][8 + wid][lane];
            float r = sigm(ir + rh);
            float z = sigm(iz + zh);
            float n = tanhf(in_ + r * nh);
            int ii = blockIdx.x * 4 + wid;
            float hv = hprev[ii * 32 + lane];
            g_eo[t * (HH * BB) + ii * 32 + lane] = (1.0f - z) * n + z * hv;
        }
        grid_sync(gridDim.x);
    }
}

// ---------------- decoder scan (phase-D weights in dynamic SMEM, gie prefetched)
__global__ void __launch_bounds__(512) dec_scan(const float* __restrict__ Whh,
                                                const float* __restrict__ bhh,
                                                const float* __restrict__ Wih,
                                                const int* __restrict__ src) {
    extern __shared__ float sWD[];
    int wid = threadIdx.x >> 5, lane = threadIdx.x & 31;
    int iLocal = wid & 3;
    int kqD = wid >> 2;
    int iD = blockIdx.x * 4 + iLocal;
    __shared__ float psA[2][8][32];
    __shared__ float psC[4][4][32];
    __shared__ float denS[32];
    __shared__ float psD[4][3][6][32];
    __shared__ float sgie[12][32];
    __shared__ float sbh[12];

    float* wrow = sWD + wid * 6 * 128;
    #pragma unroll
    for (int g = 0; g < 3; g++) {
        *(float4*)&wrow[g * 128 + lane * 4] =
            *(const float4*)(Whh + ((size_t)g * HH + iD) * HH + kqD * 128 + lane * 4);
        *(float4*)&wrow[(3 + g) * 128 + lane * 4] =
            *(const float4*)(Wih + ((size_t)g * HH + iD) * 768 + EE + kqD * 128 + lane * 4);
    }
    if (threadIdx.x < 12) {
        int g = threadIdx.x >> 2, il = threadIdx.x & 3;
        sbh[threadIdx.x] = bhh[g * HH + blockIdx.x * 4 + il];
    }
    __syncthreads();

    for (int t = 0; t < TT; t++) {
        if (threadIdx.x < 96) {
            int row = threadIdx.x >> 3, u = threadIdx.x & 7;
            int g = row >> 2, il = row & 3;
            const float* srcp = g_dec_gie + (size_t)t * (H3 * BB)
                              + ((size_t)g * HH + blockIdx.x * 4 + il) * 32 + u * 4;
            cpasync16(smem_u32(&sgie[row][u * 4]), srcp);
        }
        asm volatile("cp.async.commit_group;" ::: "memory");

        const float* h = t ? g_hdec[t & 1] : (g_eo + (SS - 1) * (HH * BB));
        {
            int s = blockIdx.x * 2 + (wid & 1);
            int kq8 = wid >> 1;
            float acc = 0.0f;
            const float* eo = g_eo + s * (HH * BB) + kq8 * 64 * 32 + lane;
            const float* hp = h + kq8 * 64 * 32 + lane;
            #pragma unroll 8
            for (int k = 0; k < 64; k++) acc += eo[k * 32] * hp[k * 32];
            psA[wid & 1][kq8][lane] = acc;
            __syncthreads();
            if (wid < 2) {
                int ss2 = blockIdx.x * 2 + wid;
                float sc = 0.0f;
                #pragma unroll
                for (int q = 0; q < 8; q++) sc += psA[wid][q][lane];
                int tokv = src[lane * SS + ss2];
                float e = (tokv == 0) ? 0.0f : __expf(sc);
                g_scores[ss2 * 32 + lane] = e;
            }
        }
        grid_sync(gridDim.x);
        {
            int k = blockIdx.x * 4 + (wid & 3);
            int sq = wid >> 2;
            float acc = 0.0f;
            const float* eo = g_eo + sq * 64 * (HH * BB) + k * 32 + lane;
            const float* sce = g_scores + sq * 64 * 32 + lane;
            #pragma unroll 8
            for (int s = 0; s < 64; s++) acc += sce[s * 32] * eo[s * (HH * BB)];
            psC[wid & 3][sq][lane] = acc;
            if (wid == 0) {
                float d = 0.0f;
                const float* sp = g_scores + lane;
                #pragma unroll 8
                for (int s = 0; s < SS; s++) d += sp[s * 32];
                denS[lane] = d;
            }
            __syncthreads();
            if (wid < 4) {
                int kk = blockIdx.x * 4 + wid;
                float c = (psC[wid][0][lane] + psC[wid][1][lane] + psC[wid][2][lane] + psC[wid][3][lane])
                          / denS[lane];
                g_ctx[kk * 32 + lane] = c;
                g_pred[(t * 32 + lane) * (2 * HH) + HH + kk] = c;
            }
        }
        grid_sync(gridDim.x);
        {
            float a0 = 0, a1 = 0, a2 = 0, c0 = 0, c1 = 0, c2 = 0;
            {
                const float* hp = h + kqD * 128 * 32 + lane;
                const float* cp = g_ctx + kqD * 128 * 32 + lane;
                #pragma unroll 4
                for (int q = 0; q < 32; q++) {
                    float h0 = hp[q * 128 + 0], h1 = hp[q * 128 + 32];
                    float h2 = hp[q * 128 + 64], h3 = hp[q * 128 + 96];
                    float x0 = cp[q * 128 + 0], x1 = cp[q * 128 + 32];
                    float x2 = cp[q * 128 + 64], x3 = cp[q * 128 + 96];
                    float4 w;
                    w = *(const float4*)&wrow[0 * 128 + q * 4];
                    a0 += w.x * h0 + w.y * h1 + w.z * h2 + w.w * h3;
                    w = *(const float4*)&wrow[1 * 128 + q * 4];
                    a1 += w.x * h0 + w.y * h1 + w.z * h2 + w.w * h3;
                    w = *(const float4*)&wrow[2 * 128 + q * 4];
                    a2 += w.x * h0 + w.y * h1 + w.z * h2 + w.w * h3;
                    w = *(const float4*)&wrow[3 * 128 + q * 4];
                    c0 += w.x * x0 + w.y * x1 + w.z * x2 + w.w * x3;
                    w = *(const float4*)&wrow[4 * 128 + q * 4];
                    c1 += w.x * x0 + w.y * x1 + w.z * x2 + w.w * x3;
                    w = *(const float4*)&wrow[5 * 128 + q * 4];
                    c2 += w.x * x0 + w.y * x1 + w.z * x2 + w.w * x3;
                }
            }
            if (kqD > 0) {
                psD[iLocal][kqD - 1][0][lane] = a0;
                psD[iLocal][kqD - 1][1][lane] = a1;
                psD[iLocal][kqD - 1][2][lane] = a2;
                psD[iLocal][kqD - 1][3][lane] = c0;
                psD[iLocal][kqD - 1][4][lane] = c1;
                psD[iLocal][kqD - 1][5][lane] = c2;
            }
            asm volatile("cp.async.wait_group 0;" ::: "memory");
            __syncthreads();
            if (wid < 4) {
                float rh = a0, zh = a1, nh = a2, rc = c0, zc = c1, nc = c2;
                #pragma unroll
                for (int kk = 0; kk < 3; kk++) {
                    rh += psD[wid][kk][0][lane];
                    zh += psD[wid][kk][1][lane];
                    nh += psD[wid][kk][2][lane];
                    rc += psD[wid][kk][3][lane];
                    zc += psD[wid][kk][4][lane];
                    nc += psD[wid][kk][5][lane];
                }
                rh += sbh[wid]; zh += sbh[4 + wid]; nh += sbh[8 + wid];
                float ir = sgie[wid][lane] + rc;
                float iz = sgie[4 + wid][lane] + zc;
                float in_ = sgie[8 + wid][lane] + nc;
                float r = sigm(ir + rh);
                float z = sigm(iz + zh);
                float n = tanhf(in_ + r * nh);
                int ii = blockIdx.x * 4 + wid;
                float hold = h[ii * 32 + lane];
                float hn = (1.0f - z) * n + z * hold;
                g_hdec[(t + 1) & 1][ii * 32 + lane] = hn;
                g_pred[(t * 32 + lane) * (2 * HH) + ii] = hn;
            }
        }
        grid_sync(gridDim.x);
    }
}

// ---------------- fc GEMM via mma.sync: 256 thr, 128x256 block, 64x64 warp tile
__global__ void __launch_bounds__(256) fc_mma(const float* __restrict__ bias,
                                              float* __restrict__ out) {
    extern __shared__ uint8_t dynsmem[];
    uint32_t sA = smem_u32(dynsmem);           // 3 x 18432
    uint32_t sB = sA + 3 * GBUF_B;             // 3 x 36864

    int tid = threadIdx.x;
    int wid = tid >> 5, lane = tid & 31;
    int wm = wid & 1, wn = wid >> 1;           // 2m x 4n warps
    int m0 = blockIdx.x * GBM;
    int n0 = blockIdx.y * FCBN;

    const char* Ag = (const char*)(g_Ab + (size_t)m0 * FCK);
    const char* Bg = (const char*)(g_Wb + (size_t)n0 * FCK);
    int lrow = tid >> 3, lu = tid & 7;

    auto load_chunk = [&](int kc, int st) {
        int seg = kc >> 4, c = kc & 15;
        size_t aoff = (size_t)(((seg == 2) ? 1024 : 0) + c * 64) * 2;
        size_t boff = (size_t)(((seg == 1) ? 1024 : 0) + c * 64) * 2;
        uint32_t sa = sA + st * GBUF_B;
        uint32_t sbm = sB + st * FCBUF;
        #pragma unroll
        for (int it = 0; it < 4; it++) {        // A: 128 rows
            int row = it * 32 + lrow;
            uint32_t doff = (uint32_t)(row * (GLDA * 2) + lu * 16);
            cpasync16(sa + doff, Ag + (size_t)row * (FCK * 2) + aoff + lu * 16);
        }
        #pragma unroll
        for (int it = 0; it < 8; it++) {        // B: 256 rows
            int row = it * 32 + lrow;
            uint32_t doff = (uint32_t)(row * (GLDA * 2) + lu * 16);
            cpasync16(sbm + doff, Bg + (size_t)row * (FCK * 2) + boff + lu * 16);
        }
        asm volatile("cp.async.commit_group;" ::: "memory");
    };

    float acc[4][8][4];
    #pragma unroll
    for (int a = 0; a < 4; a++)
        #pragma unroll
        for (int b = 0; b < 8; b++)
            #pragma unroll
            for (int c = 0; c < 4; c++) acc[a][b][c] = 0.0f;

    uint32_t aBase = (uint32_t)(((wm * 64 + (lane & 15)) * GLDA + (lane >> 4) * 8) * 2);
    uint32_t bBase = (uint32_t)(((wn * 64 + (lane & 7) + ((lane >> 4) & 1) * 8) * GLDA
                                 + ((lane >> 3) & 1) * 8) * 2);

    load_chunk(0, 0);
    load_chunk(1, 1);
    for (int kc = 0; kc < FC_NC; kc++) {
        int st = kc % 3;
        if (kc == FC_NC - 1) { asm volatile("cp.async.wait_group 0;" ::: "memory"); }
        else                 { asm volatile("cp.async.wait_group 1;" ::: "memory"); }
        __syncthreads();
        if (kc + 2 < FC_NC) load_chunk(kc + 2, (kc + 2) % 3);
        uint32_t sa = sA + st * GBUF_B + aBase;
        uint32_t sbm = sB + st * FCBUF + bBase;
        #pragma unroll
        for (int ks = 0; ks < 4; ks++) {
            uint32_t koff = (uint32_t)(ks * 16 * 2);
            uint32_t af[4][4];
            #pragma unroll
            for (int mt = 0; mt < 4; mt++)
                LDSM4(af[mt][0], af[mt][1], af[mt][2], af[mt][3],
                      sa + mt * 16 * GLDA * 2 + koff);
            uint32_t bf[16];
            #pragma unroll
            for (int nt = 0; nt < 4; nt++)
                LDSM4(bf[nt * 4 + 0], bf[nt * 4 + 1], bf[nt * 4 + 2], bf[nt * 4 + 3],
                      sbm + nt * 16 * GLDA * 2 + koff);
            #pragma unroll
            for (int mt = 0; mt < 4; mt++)
                #pragma unroll
                for (int j = 0; j < 8; j++) {
                    int nt = j >> 1, hf = j & 1;
                    MMA16816(acc[mt][j], af[mt], bf[nt * 4 + hf * 2], bf[nt * 4 + hf * 2 + 1]);
                }
        }
    }
    __syncthreads();

    float bv[8][2];
    #pragma unroll
    for (int j = 0; j < 8; j++) {
        int n = n0 + wn * 64 + j * 8 + (lane & 3) * 2;
        bv[j][0] = __ldg(bias + n);
        bv[j][1] = __ldg(bias + n + 1);
    }
    #pragma unroll
    for (int mt = 0; mt < 4; mt++) {
        #pragma unroll
        for (int half = 0; half < 2; half++) {
            int m = m0 + wm * 64 + mt * 16 + (lane >> 2) + half * 8;
            int t = m >> 5, b = m & 31;
            float* orow = out + (size_t)b * (TT * VV) + (size_t)t * VV;
            #pragma unroll
            for (int j = 0; j < 8; j++) {
                int n = n0 + wn * 64 + j * 8 + (lane & 3) * 2;
                float2 v;
                v.x = acc[mt][j][half * 2 + 0] + bv[j][0];
                v.y = acc[mt][j][half * 2 + 1] + bv[j][1];
                *(float2*)(orow + n) = v;
            }
        }
    }
}

// ---------------- launch (dual-stream overlap: dec prep + convW hide under enc) --
extern "C" void kernel_launch(void* const* d_in, const int* in_sizes, int n_in,
                              void* d_out, int out_size) {
    const int* src = (const int*)d_in[0];
    const int* tgt = (const int*)d_in[2];
    const float* enc_emb = (const float*)d_in[3];
    const float* enc_Wih = (const float*)d_in[4];
    const float* enc_Whh = (const float*)d_in[5];
    const float* enc_bih = (const float*)d_in[6];
    const float* enc_bhh = (const float*)d_in[7];
    const float* dec_emb = (const float*)d_in[8];
    const float* dec_Wih = (const float*)d_in[9];
    const float* dec_Whh = (const float*)d_in[10];
    const float* dec_bih = (const float*)d_in[11];
    const float* dec_bhh = (const float*)d_in[12];
    const float* fc_W = (const float*)d_in[13];
    const float* fc_b = (const float*)d_in[14];
    float* out = (float*)d_out;

    static cudaStream_t s2 = nullptr;
    static cudaEvent_t evFork = nullptr, evJoin = nullptr;
    static bool attrs_set = false;
    if (!s2) {
        cudaStreamCreateWithFlags(&s2, cudaStreamNonBlocking);
        cudaEventCreateWithFlags(&evFork, cudaEventDisableTiming);
        cudaEventCreateWithFlags(&evJoin, cudaEventDisableTiming);
    }
    if (!attrs_set) {
        cudaFuncSetAttribute(fc_mma, cudaFuncAttributeMaxDynamicSharedMemorySize, FC_SMEM3);
        cudaFuncSetAttribute(gi_mma, cudaFuncAttributeMaxDynamicSharedMemorySize, MM_SMEM);
        cudaFuncSetAttribute(dec_scan, cudaFuncAttributeMaxDynamicSharedMemorySize, DEC_WSMEM);
        attrs_set = true;
    }

    // fork: dec-side prep + convW on s2
    cudaEventRecord(evFork, 0);
    cudaStreamWaitEvent(s2, evFork, 0);
    gatherX<<<TT * BB / 8, 256, 0, s2>>>(dec_emb, tgt, TT, 1);
    splitWih<<<H3 / 8, 256, 0, s2>>>(dec_Wih, EE + HH, 1);
    gi_mma<<<dim3(TT * BB / GBM, H3 / GBN), 256, MM_SMEM, s2>>>(dec_bih, 1);
    convW<<<(VV * 256) / 1024, 1024, 0, s2>>>(fc_W);
    cudaEventRecord(evJoin, s2);

    // main: enc path
    gatherX<<<SS * BB / 8, 256>>>(enc_emb, src, SS, 0);
    splitWih<<<H3 / 8, 256>>>(enc_Wih, EE, 0);
    gi_mma<<<dim3(SS * BB / GBM, H3 / GBN), 256, MM_SMEM>>>(enc_bih, 0);
    enc_scan<<<NCTA, 512>>>(enc_Whh, enc_bhh);

    // join, then decoder + fc
    cudaStreamWaitEvent(0, evJoin, 0);
    dec_scan<<<NCTA, 512, DEC_WSMEM>>>(dec_Whh, dec_bhh, dec_Wih, src);
    convA<<<512, 1024>>>();
    fc_mma<<<dim3(TT * BB / GBM, VV / FCBN), 256, FC_SMEM3>>>(fc_b, out);
}

// round 15
// speedup vs baseline: 1.0103x; 1.0103x over previous
#include <cuda_runtime.h>
#include <cuda_bf16.h>
#include <cstdint>

// Problem constants
#define BB 32
#define SS 256
#define TT 64
#define EE 256
#define HH 512
#define VV 32000
#define H3 1536

// GEMM tile config
#define GBM 128
#define GBN 128
#define GBK 64
#define GLDA 72                 // padded row (bf16 elems)
#define GBUF_B (GBM * GLDA * 2) // 18432 bytes (128-row stage buffer)
#define MM_SMEM (6 * GBUF_B)    // gi: 3 stages x (A+B) = 110592

// fc: 128x256 block, 64x64 warp tile, 256 thr, 3-stage
#define FCBN 256
#define FCBUF (FCBN * GLDA * 2)            // 36864
#define FC_SMEM3 (3 * GBUF_B + 3 * FCBUF)  // 165888

// K layouts (deduplicated): stored [hi | lo]
#define FCK 2048
#define GIX 512
#define FC_NC 48                // 3 segments x 16 chunks
#define GI_NC 12

#define NCTA 128
#define DEC_WSMEM 49152

// ---------------- scratch ----------------
__device__ float g_enc_gi[SS * H3 * BB];
__device__ float g_dec_gie[TT * H3 * BB];
__device__ float g_eo[SS * HH * BB];
__device__ float g_h0[HH * BB];          // never written -> stays zero
__device__ float g_hdec[2][HH * BB];
__device__ float g_ctx[HH * BB];
__device__ float g_scores[SS * BB];
__device__ float g_pred[(TT * BB) * (2 * HH)];
__device__ __nv_bfloat16 g_Wb[(size_t)VV * FCK];
__device__ __nv_bfloat16 g_Ab[(size_t)(TT * BB) * FCK];
__device__ __nv_bfloat16 g_Xe[(size_t)(SS * BB) * GIX];
__device__ __nv_bfloat16 g_Xd[(size_t)(TT * BB) * GIX];
__device__ __nv_bfloat16 g_We[(size_t)H3 * GIX];
__device__ __nv_bfloat16 g_Wd[(size_t)H3 * GIX];
__device__ unsigned g_bar_cnt;
__device__ unsigned g_bar_gen;

// ---------------- grid barrier (proven) ----------------
__device__ __forceinline__ void grid_sync(unsigned nb) {
    __syncthreads();
    if (threadIdx.x == 0) {
        __threadfence();
        volatile unsigned* genp = &g_bar_gen;
        unsigned gen = *genp;
        if (atomicAdd(&g_bar_cnt, 1u) == nb - 1u) {
            g_bar_cnt = 0;
            __threadfence();
            *genp = gen + 1u;
        } else {
            while (*genp == gen) { }
            __threadfence();
        }
    }
    __syncthreads();
}

__device__ __forceinline__ float sigm(float x) { return 1.0f / (1.0f + __expf(-x)); }

__device__ __forceinline__ uint32_t smem_u32(const void* p) {
    uint32_t a;
    asm("{ .reg .u64 t; cvta.to.shared.u64 t, %1; cvt.u32.u64 %0, t; }" : "=r"(a) : "l"(p));
    return a;
}
__device__ __forceinline__ void cpasync16(uint32_t dst, const void* src) {
    asm volatile("cp.async.cg.shared.global [%0], [%1], 16;" :: "r"(dst), "l"(src) : "memory");
}
#define LDSM4(r0, r1, r2, r3, addr) \
    asm volatile("ldmatrix.sync.aligned.m8n8.x4.shared.b16 {%0,%1,%2,%3}, [%4];" \
                 : "=r"(r0), "=r"(r1), "=r"(r2), "=r"(r3) : "r"(addr))
#define MMA16816(c, a, b0, b1) \
    asm volatile("mma.sync.aligned.m16n8k16.row.col.f32.bf16.bf16.f32 " \
                 "{%0,%1,%2,%3}, {%4,%5,%6,%7}, {%8,%9}, {%0,%1,%2,%3};" \
                 : "+f"((c)[0]), "+f"((c)[1]), "+f"((c)[2]), "+f"((c)[3]) \
                 : "r"((a)[0]), "r"((a)[1]), "r"((a)[2]), "r"((a)[3]), "r"(b0), "r"(b1))

__device__ __forceinline__ void split4(float4 v, __nv_bfloat162& hA, __nv_bfloat162& hB,
                                       __nv_bfloat162& lA, __nv_bfloat162& lB) {
    __nv_bfloat16 h0 = __float2bfloat16(v.x), h1 = __float2bfloat16(v.y);
    __nv_bfloat16 h2 = __float2bfloat16(v.z), h3 = __float2bfloat16(v.w);
    __nv_bfloat16 l0 = __float2bfloat16(v.x - __bfloat162float(h0));
    __nv_bfloat16 l1 = __float2bfloat16(v.y - __bfloat162float(h1));
    __nv_bfloat16 l2 = __float2bfloat16(v.z - __bfloat162float(h2));
    __nv_bfloat16 l3 = __float2bfloat16(v.w - __bfloat162float(h3));
    hA = {h0, h1}; hB = {h2, h3}; lA = {l0, l1}; lB = {l2, l3};
}

// ---------------- W split: g_Wb[n] = [hi | lo]
__global__ void convW(const float* __restrict__ W) {
    size_t i = (size_t)blockIdx.x * 1024 + threadIdx.x;
    float4 v = ((const float4*)W)[i];
    size_t n = i >> 8;
    size_t k4 = (i & 255) * 4;
    __nv_bfloat162 hA, hB, lA, lB;
    split4(v, hA, hB, lA, lB);
    __nv_bfloat16* dst = g_Wb + n * FCK;
    *(__nv_bfloat162*)(dst + k4) = hA;          *(__nv_bfloat162*)(dst + k4 + 2) = hB;
    *(__nv_bfloat162*)(dst + 1024 + k4) = lA;   *(__nv_bfloat162*)(dst + 1024 + k4 + 2) = lB;
}

// ---------------- pred split: g_Ab[m] = [hi | lo]
__global__ void convA() {
    size_t i = (size_t)blockIdx.x * 1024 + threadIdx.x;
    float4 v = ((const float4*)g_pred)[i];
    size_t m = i >> 8;
    size_t k4 = (i & 255) * 4;
    __nv_bfloat162 hA, hB, lA, lB;
    split4(v, hA, hB, lA, lB);
    __nv_bfloat16* dst = g_Ab + m * FCK;
    *(__nv_bfloat162*)(dst + k4) = hA;          *(__nv_bfloat162*)(dst + k4 + 2) = hB;
    *(__nv_bfloat162*)(dst + 1024 + k4) = lA;   *(__nv_bfloat162*)(dst + 1024 + k4 + 2) = lB;
}

// ---------------- gather embedding rows + split
__global__ void gatherX(const float* __restrict__ emb, const int* __restrict__ tok,
                        int L, int which) {
    __nv_bfloat16* X = which ? g_Xd : g_Xe;
    int m = blockIdx.x * 8 + (threadIdx.x >> 5);
    int lane = threadIdx.x & 31;
    int t = m >> 5, b = m & 31;
    int tv = tok[b * L + t];
    const float4* er = (const float4*)(emb + (size_t)tv * EE);
    __nv_bfloat16* dst = X + (size_t)m * GIX;
    #pragma unroll
    for (int q = 0; q < 2; q++) {
        float4 v = er[lane * 2 + q];
        int e = lane * 8 + q * 4;
        __nv_bfloat162 hA, hB, lA, lB;
        split4(v, hA, hB, lA, lB);
        *(__nv_bfloat162*)(dst + e) = hA;            *(__nv_bfloat162*)(dst + e + 2) = hB;
        *(__nv_bfloat162*)(dst + 256 + e) = lA;      *(__nv_bfloat162*)(dst + 256 + e + 2) = lB;
    }
}

// ---------------- split Wih rows (first 256 cols)
__global__ void splitWih(const float* __restrict__ W, int stride, int which) {
    __nv_bfloat16* out = which ? g_Wd : g_We;
    int j = blockIdx.x * 8 + (threadIdx.x >> 5);
    int lane = threadIdx.x & 31;
    const float4* wr = (const float4*)(W + (size_t)j * stride);
    __nv_bfloat16* dst = out + (size_t)j * GIX;
    #pragma unroll
    for (int q = 0; q < 2; q++) {
        float4 v = wr[lane * 2 + q];
        int e = lane * 8 + q * 4;
        __nv_bfloat162 hA, hB, lA, lB;
        split4(v, hA, hB, lA, lB);
        *(__nv_bfloat162*)(dst + e) = hA;            *(__nv_bfloat162*)(dst + e + 2) = hB;
        *(__nv_bfloat162*)(dst + 256 + e) = lA;      *(__nv_bfloat162*)(dst + 256 + e + 2) = lB;
    }
}

// ---------------- gi GEMM via HMMA (256 thr, 128x128, K eff 768)
__global__ void __launch_bounds__(256) gi_mma(const float* __restrict__ bih, int which) {
    extern __shared__ uint8_t dynsmem[];
    uint32_t sA = smem_u32(dynsmem);
    uint32_t sB = sA + 3 * GBUF_B;

    const __nv_bfloat16* A = which ? g_Xd : g_Xe;
    const __nv_bfloat16* Bm = which ? g_Wd : g_We;
    float* outg = which ? g_dec_gie : g_enc_gi;

    int tid = threadIdx.x;
    int wid = tid >> 5, lane = tid & 31;
    int wm = wid & 3, wn = wid >> 2;
    int m0 = blockIdx.x * GBM;
    int n0 = blockIdx.y * GBN;

    const char* Ag = (const char*)(A + (size_t)m0 * GIX);
    const char* Bg = (const char*)(Bm + (size_t)n0 * GIX);
    int lrow = tid >> 3, lu = tid & 7;

    auto load_chunk = [&](int kc, int st) {
        int seg = kc >> 2, c = kc & 3;
        size_t aoff = (size_t)(((seg == 2) ? 256 : 0) + c * 64) * 2;
        size_t boff = (size_t)(((seg == 1) ? 256 : 0) + c * 64) * 2;
        uint32_t sa = sA + st * GBUF_B;
        uint32_t sbm = sB + st * GBUF_B;
        #pragma unroll
        for (int it = 0; it < 4; it++) {
            int row = it * 32 + lrow;
            uint32_t doff = (uint32_t)(row * (GLDA * 2) + lu * 16);
            cpasync16(sa + doff, Ag + (size_t)row * (GIX * 2) + aoff + lu * 16);
            cpasync16(sbm + doff, Bg + (size_t)row * (GIX * 2) + boff + lu * 16);
        }
        asm volatile("cp.async.commit_group;" ::: "memory");
    };

    float acc[2][8][4];
    #pragma unroll
    for (int a = 0; a < 2; a++)
        #pragma unroll
        for (int b = 0; b < 8; b++)
            #pragma unroll
            for (int c = 0; c < 4; c++) acc[a][b][c] = 0.0f;

    uint32_t aBase = (uint32_t)(((wm * 32 + (lane & 15)) * GLDA + (lane >> 4) * 8) * 2);
    uint32_t bBase = (uint32_t)(((wn * 64 + (lane & 7) + ((lane >> 4) & 1) * 8) * GLDA
                                 + ((lane >> 3) & 1) * 8) * 2);

    load_chunk(0, 0);
    load_chunk(1, 1);
    for (int kc = 0; kc < GI_NC; kc++) {
        int st = kc % 3;
        if (kc == GI_NC - 1) { asm volatile("cp.async.wait_group 0;" ::: "memory"); }
        else                 { asm volatile("cp.async.wait_group 1;" ::: "memory"); }
        __syncthreads();
        if (kc + 2 < GI_NC) load_chunk(kc + 2, (kc + 2) % 3);
        uint32_t sa = sA + st * GBUF_B + aBase;
        uint32_t sbm = sB + st * GBUF_B + bBase;
        #pragma unroll
        for (int ks = 0; ks < 4; ks++) {
            uint32_t koff = (uint32_t)(ks * 16 * 2);
            uint32_t a0[4], a1[4];
            LDSM4(a0[0], a0[1], a0[2], a0[3], sa + koff);
            LDSM4(a1[0], a1[1], a1[2], a1[3], sa + 16 * GLDA * 2 + koff);
            uint32_t bf[16];
            #pragma unroll
            for (int nt = 0; nt < 4; nt++)
                LDSM4(bf[nt * 4 + 0], bf[nt * 4 + 1], bf[nt * 4 + 2], bf[nt * 4 + 3],
                      sbm + nt * 16 * GLDA * 2 + koff);
            #pragma unroll
            for (int j = 0; j < 8; j++) {
                int nt = j >> 1, hf = j & 1;
                MMA16816(acc[0][j], a0, bf[nt * 4 + hf * 2], bf[nt * 4 + hf * 2 + 1]);
                MMA16816(acc[1][j], a1, bf[nt * 4 + hf * 2], bf[nt * 4 + hf * 2 + 1]);
            }
        }
    }
    __syncthreads();

    #pragma unroll
    for (int mt = 0; mt < 2; mt++) {
        #pragma unroll
        for (int half = 0; half < 2; half++) {
            int m = m0 + wm * 32 + mt * 16 + (lane >> 2) + half * 8;
            int t = m >> 5, b = m & 31;
            float* obase = outg + (size_t)t * (H3 * BB) + b;
            #pragma unroll
            for (int j = 0; j < 8; j++) {
                int n = n0 + wn * 64 + j * 8 + (lane & 3) * 2;
                obase[(size_t)n * 32] = acc[mt][j][half * 2 + 0] + __ldg(bih + n);
                obase[(size_t)(n + 1) * 32] = acc[mt][j][half * 2 + 1] + __ldg(bih + n + 1);
            }
        }
    }
}

// ---------------- encoder scan (weights in SMEM, gi prefetched) ----------------
__global__ void __launch_bounds__(512) enc_scan(const float* __restrict__ Whh,
                                                const float* __restrict__ bhh) {
    int wid = threadIdx.x >> 5, lane = threadIdx.x & 31;
    int iLocal = wid & 3;
    int kq = wid >> 2;
    int i = blockIdx.x * 4 + iLocal;
    __shared__ float sW[16][3][128];
    __shared__ float ps[4][3][3][32];
    __shared__ float sgi[2][12][32];
    __shared__ float sbh[12];

    #pragma unroll
    for (int g = 0; g < 3; g++) {
        float4 w = *(const float4*)(Whh + ((size_t)g * HH + i) * HH + kq * 128 + lane * 4);
        *(float4*)&sW[wid][g][lane * 4] = w;
    }
    if (threadIdx.x < 12) {
        int g = threadIdx.x >> 2, il = threadIdx.x & 3;
        sbh[threadIdx.x] = bhh[g * HH + blockIdx.x * 4 + il];
    }

    auto prefetch_gi = [&](int t, int buf) {
        if (threadIdx.x < 96) {
            int row = threadIdx.x >> 3, u = threadIdx.x & 7;
            int g = row >> 2, il = row & 3;
            const float* src = g_enc_gi + (size_t)t * (H3 * BB)
                             + ((size_t)g * HH + blockIdx.x * 4 + il) * 32 + u * 4;
            cpasync16(smem_u32(&sgi[buf][row][u * 4]), src);
        }
        asm volatile("cp.async.commit_group;" ::: "memory");
    };
    prefetch_gi(0, 0);
    __syncthreads();

    for (int t = 0; t < SS; t++) {
        if (t + 1 < SS) prefetch_gi(t + 1, (t + 1) & 1);
        const float* hprev = t ? (g_eo + (t - 1) * (HH * BB)) : g_h0;
        const float* hp = hprev + kq * 128 * 32 + lane;
        float s0 = 0, s1 = 0, s2 = 0;
        #pragma unroll 8
        for (int q = 0; q < 32; q++) {
            float h0 = hp[q * 128 + 0];
            float h1 = hp[q * 128 + 32];
            float h2 = hp[q * 128 + 64];
            float h3 = hp[q * 128 + 96];
            float4 w0 = *(const float4*)&sW[wid][0][q * 4];
            float4 w1 = *(const float4*)&sW[wid][1][q * 4];
            float4 w2 = *(const float4*)&sW[wid][2][q * 4];
            s0 += w0.x * h0 + w0.y * h1 + w0.z * h2 + w0.w * h3;
            s1 += w1.x * h0 + w1.y * h1 + w1.z * h2 + w1.w * h3;
            s2 += w2.x * h0 + w2.y * h1 + w2.z * h2 + w2.w * h3;
        }
        if (kq > 0) {
            ps[iLocal][kq - 1][0][lane] = s0;
            ps[iLocal][kq - 1][1][lane] = s1;
            ps[iLocal][kq - 1][2][lane] = s2;
        }
        asm volatile("cp.async.wait_group 1;" ::: "memory");
        __syncthreads();
        if (wid < 4) {
            float rh = s0 + ps[wid][0][0][lane] + ps[wid][1][0][lane] + ps[wid][2][0][lane] + sbh[wid];
            float zh = s1 + ps[wid][0][1][lane] + ps[wid][1][1][lane] + ps[wid][2][1][lane] + sbh[4 + wid];
            float nh = s2 + ps[wid][0][2][lane] + ps[wid][1][2][lane] + ps[wid][2][2][lane] + sbh[8 + wid];
            float ir = sgi[t & 1][wid][lane];
            float iz = sgi[t & 1][4 + wid][lane];
            float in_ = sgi[t & 1][8 + wid][lane];
            float r = sigm(ir + rh);
            float z = sigm(iz + zh);
            float n = tanhf(in_ + r * nh);
            int ii = blockIdx.x * 4 + wid;
            float hv = hprev[ii * 32 + lane];
            g_eo[t * (HH * BB) + ii * 32 + lane] = (1.0f - z) * n + z * hv;
        }
        grid_sync(gridDim.x);
    }
}

// ---------------- decoder scan (phase-D weights in dynamic SMEM, gie prefetched)
__global__ void __launch_bounds__(512) dec_scan(const float* __restrict__ Whh,
                                                const float* __restrict__ bhh,
                                                const float* __restrict__ Wih,
                                                const int* __restrict__ src) {
    extern __shared__ float sWD[];
    int wid = threadIdx.x >> 5, lane = threadIdx.x & 31;
    int iLocal = wid & 3;
    int kqD = wid >> 2;
    int iD = blockIdx.x * 4 + iLocal;
    __shared__ float psA[2][8][32];
    __shared__ float psC[4][4][32];
    __shared__ float denS[32];
    __shared__ float psD[4][3][6][32];
    __shared__ float sgie[12][32];
    __shared__ float sbh[12];

    float* wrow = sWD + wid * 6 * 128;
    #pragma unroll
    for (int g = 0; g < 3; g++) {
        *(float4*)&wrow[g * 128 + lane * 4] =
            *(const float4*)(Whh + ((size_t)g * HH + iD) * HH + kqD * 128 + lane * 4);
        *(float4*)&wrow[(3 + g) * 128 + lane * 4] =
            *(const float4*)(Wih + ((size_t)g * HH + iD) * 768 + EE + kqD * 128 + lane * 4);
    }
    if (threadIdx.x < 12) {
        int g = threadIdx.x >> 2, il = threadIdx.x & 3;
        sbh[threadIdx.x] = bhh[g * HH + blockIdx.x * 4 + il];
    }
    __syncthreads();

    for (int t = 0; t < TT; t++) {
        if (threadIdx.x < 96) {
            int row = threadIdx.x >> 3, u = threadIdx.x & 7;
            int g = row >> 2, il = row & 3;
            const float* srcp = g_dec_gie + (size_t)t * (H3 * BB)
                              + ((size_t)g * HH + blockIdx.x * 4 + il) * 32 + u * 4;
            cpasync16(smem_u32(&sgie[row][u * 4]), srcp);
        }
        asm volatile("cp.async.commit_group;" ::: "memory");

        const float* h = t ? g_hdec[t & 1] : (g_eo + (SS - 1) * (HH * BB));
        {
            int s = blockIdx.x * 2 + (wid & 1);
            int kq8 = wid >> 1;
            float acc = 0.0f;
            const float* eo = g_eo + s * (HH * BB) + kq8 * 64 * 32 + lane;
            const float* hp = h + kq8 * 64 * 32 + lane;
            #pragma unroll 8
            for (int k = 0; k < 64; k++) acc += eo[k * 32] * hp[k * 32];
            psA[wid & 1][kq8][lane] = acc;
            __syncthreads();
            if (wid < 2) {
                int ss2 = blockIdx.x * 2 + wid;
                float sc = 0.0f;
                #pragma unroll
                for (int q = 0; q < 8; q++) sc += psA[wid][q][lane];
                int tokv = src[lane * SS + ss2];
                float e = (tokv == 0) ? 0.0f : __expf(sc);
                g_scores[ss2 * 32 + lane] = e;
            }
        }
        grid_sync(gridDim.x);
        {
            int k = blockIdx.x * 4 + (wid & 3);
            int sq = wid >> 2;
            float acc = 0.0f;
            const float* eo = g_eo + sq * 64 * (HH * BB) + k * 32 + lane;
            const float* sce = g_scores + sq * 64 * 32 + lane;
            #pragma unroll 8
            for (int s = 0; s < 64; s++) acc += sce[s * 32] * eo[s * (HH * BB)];
            psC[wid & 3][sq][lane] = acc;
            if (wid == 0) {
                float d = 0.0f;
                const float* sp = g_scores + lane;
                #pragma unroll 8
                for (int s = 0; s < SS; s++) d += sp[s * 32];
                denS[lane] = d;
            }
            __syncthreads();
            if (wid < 4) {
                int kk = blockIdx.x * 4 + wid;
                float c = (psC[wid][0][lane] + psC[wid][1][lane] + psC[wid][2][lane] + psC[wid][3][lane])
                          / denS[lane];
                g_ctx[kk * 32 + lane] = c;
                g_pred[(t * 32 + lane) * (2 * HH) + HH + kk] = c;
            }
        }
        grid_sync(gridDim.x);
        {
            float a0 = 0, a1 = 0, a2 = 0, c0 = 0, c1 = 0, c2 = 0;
            {
                const float* hp = h + kqD * 128 * 32 + lane;
                const float* cp = g_ctx + kqD * 128 * 32 + lane;
                #pragma unroll 4
                for (int q = 0; q < 32; q++) {
                    float h0 = hp[q * 128 + 0], h1 = hp[q * 128 + 32];
                    float h2 = hp[q * 128 + 64], h3 = hp[q * 128 + 96];
                    float x0 = cp[q * 128 + 0], x1 = cp[q * 128 + 32];
                    float x2 = cp[q * 128 + 64], x3 = cp[q * 128 + 96];
                    float4 w;
                    w = *(const float4*)&wrow[0 * 128 + q * 4];
                    a0 += w.x * h0 + w.y * h1 + w.z * h2 + w.w * h3;
                    w = *(const float4*)&wrow[1 * 128 + q * 4];
                    a1 += w.x * h0 + w.y * h1 + w.z * h2 + w.w * h3;
                    w = *(const float4*)&wrow[2 * 128 + q * 4];
                    a2 += w.x * h0 + w.y * h1 + w.z * h2 + w.w * h3;
                    w = *(const float4*)&wrow[3 * 128 + q * 4];
                    c0 += w.x * x0 + w.y * x1 + w.z * x2 + w.w * x3;
                    w = *(const float4*)&wrow[4 * 128 + q * 4];
                    c1 += w.x * x0 + w.y * x1 + w.z * x2 + w.w * x3;
                    w = *(const float4*)&wrow[5 * 128 + q * 4];
                    c2 += w.x * x0 + w.y * x1 + w.z * x2 + w.w * x3;
                }
            }
            if (kqD > 0) {
                psD[iLocal][kqD - 1][0][lane] = a0;
                psD[iLocal][kqD - 1][1][lane] = a1;
                psD[iLocal][kqD - 1][2][lane] = a2;
                psD[iLocal][kqD - 1][3][lane] = c0;
                psD[iLocal][kqD - 1][4][lane] = c1;
                psD[iLocal][kqD - 1][5][lane] = c2;
            }
            asm volatile("cp.async.wait_group 0;" ::: "memory");
            __syncthreads();
            if (wid < 4) {
                float rh = a0, zh = a1, nh = a2, rc = c0, zc = c1, nc = c2;
                #pragma unroll
                for (int kk = 0; kk < 3; kk++) {
                    rh += psD[wid][kk][0][lane];
                    zh += psD[wid][kk][1][lane];
                    nh += psD[wid][kk][2][lane];
                    rc += psD[wid][kk][3][lane];
                    zc += psD[wid][kk][4][lane];
                    nc += psD[wid][kk][5][lane];
                }
                rh += sbh[wid]; zh += sbh[4 + wid]; nh += sbh[8 + wid];
                float ir = sgie[wid][lane] + rc;
                float iz = sgie[4 + wid][lane] + zc;
                float in_ = sgie[8 + wid][lane] + nc;
                float r = sigm(ir + rh);
                float z = sigm(iz + zh);
                float n = tanhf(in_ + r * nh);
                int ii = blockIdx.x * 4 + wid;
                float hold = h[ii * 32 + lane];
                float hn = (1.0f - z) * n + z * hold;
                g_hdec[(t + 1) & 1][ii * 32 + lane] = hn;
                g_pred[(t * 32 + lane) * (2 * HH) + ii] = hn;
            }
        }
        grid_sync(gridDim.x);
    }
}

// ---------------- fc GEMM via mma.sync: 256 thr, 128x256 block, 64x64 warp tile
__global__ void __launch_bounds__(256) fc_mma(const float* __restrict__ bias,
                                              float* __restrict__ out) {
    extern __shared__ uint8_t dynsmem[];
    uint32_t sA = smem_u32(dynsmem);           // 3 x 18432
    uint32_t sB = sA + 3 * GBUF_B;             // 3 x 36864

    int tid = threadIdx.x;
    int wid = tid >> 5, lane = tid & 31;
    int wm = wid & 1, wn = wid >> 1;           // 2m x 4n warps
    int m0 = blockIdx.x * GBM;
    int n0 = blockIdx.y * FCBN;

    const char* Ag = (const char*)(g_Ab + (size_t)m0 * FCK);
    const char* Bg = (const char*)(g_Wb + (size_t)n0 * FCK);
    int lrow = tid >> 3, lu = tid & 7;

    auto load_chunk = [&](int kc, int st) {
        int seg = kc >> 4, c = kc & 15;
        size_t aoff = (size_t)(((seg == 2) ? 1024 : 0) + c * 64) * 2;
        size_t boff = (size_t)(((seg == 1) ? 1024 : 0) + c * 64) * 2;
        uint32_t sa = sA + st * GBUF_B;
        uint32_t sbm = sB + st * FCBUF;
        #pragma unroll
        for (int it = 0; it < 4; it++) {        // A: 128 rows
            int row = it * 32 + lrow;
            uint32_t doff = (uint32_t)(row * (GLDA * 2) + lu * 16);
            cpasync16(sa + doff, Ag + (size_t)row * (FCK * 2) + aoff + lu * 16);
        }
        #pragma unroll
        for (int it = 0; it < 8; it++) {        // B: 256 rows
            int row = it * 32 + lrow;
            uint32_t doff = (uint32_t)(row * (GLDA * 2) + lu * 16);
            cpasync16(sbm + doff, Bg + (size_t)row * (FCK * 2) + boff + lu * 16);
        }
        asm volatile("cp.async.commit_group;" ::: "memory");
    };

    float acc[4][8][4];
    #pragma unroll
    for (int a = 0; a < 4; a++)
        #pragma unroll
        for (int b = 0; b < 8; b++)
            #pragma unroll
            for (int c = 0; c < 4; c++) acc[a][b][c] = 0.0f;

    uint32_t aBase = (uint32_t)(((wm * 64 + (lane & 15)) * GLDA + (lane >> 4) * 8) * 2);
    uint32_t bBase = (uint32_t)(((wn * 64 + (lane & 7) + ((lane >> 4) & 1) * 8) * GLDA
                                 + ((lane >> 3) & 1) * 8) * 2);

    load_chunk(0, 0);
    load_chunk(1, 1);
    for (int kc = 0; kc < FC_NC; kc++) {
        int st = kc % 3;
        if (kc == FC_NC - 1) { asm volatile("cp.async.wait_group 0;" ::: "memory"); }
        else                 { asm volatile("cp.async.wait_group 1;" ::: "memory"); }
        __syncthreads();
        if (kc + 2 < FC_NC) load_chunk(kc + 2, (kc + 2) % 3);
        uint32_t sa = sA + st * GBUF_B + aBase;
        uint32_t sbm = sB + st * FCBUF + bBase;
        #pragma unroll
        for (int ks = 0; ks < 4; ks++) {
            uint32_t koff = (uint32_t)(ks * 16 * 2);
            uint32_t af[4][4];
            #pragma unroll
            for (int mt = 0; mt < 4; mt++)
                LDSM4(af[mt][0], af[mt][1], af[mt][2], af[mt][3],
                      sa + mt * 16 * GLDA * 2 + koff);
            uint32_t bf[16];
            #pragma unroll
            for (int nt = 0; nt < 4; nt++)
                LDSM4(bf[nt * 4 + 0], bf[nt * 4 + 1], bf[nt * 4 + 2], bf[nt * 4 + 3],
                      sbm + nt * 16 * GLDA * 2 + koff);
            #pragma unroll
            for (int mt = 0; mt < 4; mt++)
                #pragma unroll
                for (int j = 0; j < 8; j++) {
                    int nt = j >> 1, hf = j & 1;
                    MMA16816(acc[mt][j], af[mt], bf[nt * 4 + hf * 2], bf[nt * 4 + hf * 2 + 1]);
                }
        }
    }
    __syncthreads();

    float bv[8][2];
    #pragma unroll
    for (int j = 0; j < 8; j++) {
        int n = n0 + wn * 64 + j * 8 + (lane & 3) * 2;
        bv[j][0] = __ldg(bias + n);
        bv[j][1] = __ldg(bias + n + 1);
    }
    #pragma unroll
    for (int mt = 0; mt < 4; mt++) {
        #pragma unroll
        for (int half = 0; half < 2; half++) {
            int m = m0 + wm * 64 + mt * 16 + (lane >> 2) + half * 8;
            int t = m >> 5, b = m & 31;
            float* orow = out + (size_t)b * (TT * VV) + (size_t)t * VV;
            #pragma unroll
            for (int j = 0; j < 8; j++) {
                int n = n0 + wn * 64 + j * 8 + (lane & 3) * 2;
                float2 v;
                v.x = acc[mt][j][half * 2 + 0] + bv[j][0];
                v.y = acc[mt][j][half * 2 + 1] + bv[j][1];
                *(float2*)(orow + n) = v;
            }
        }
    }
}

// ---------------- launch (serial; stream overlap reverted) ----------------
extern "C" void kernel_launch(void* const* d_in, const int* in_sizes, int n_in,
                              void* d_out, int out_size) {
    const int* src = (const int*)d_in[0];
    const int* tgt = (const int*)d_in[2];
    const float* enc_emb = (const float*)d_in[3];
    const float* enc_Wih = (const float*)d_in[4];
    const float* enc_Whh = (const float*)d_in[5];
    const float* enc_bih = (const float*)d_in[6];
    const float* enc_bhh = (const float*)d_in[7];
    const float* dec_emb = (const float*)d_in[8];
    const float* dec_Wih = (const float*)d_in[9];
    const float* dec_Whh = (const float*)d_in[10];
    const float* dec_bih = (const float*)d_in[11];
    const float* dec_bhh = (const float*)d_in[12];
    const float* fc_W = (const float*)d_in[13];
    const float* fc_b = (const float*)d_in[14];
    float* out = (float*)d_out;

    cudaFuncSetAttribute(fc_mma, cudaFuncAttributeMaxDynamicSharedMemorySize, FC_SMEM3);
    cudaFuncSetAttribute(gi_mma, cudaFuncAttributeMaxDynamicSharedMemorySize, MM_SMEM);
    cudaFuncSetAttribute(dec_scan, cudaFuncAttributeMaxDynamicSharedMemorySize, DEC_WSMEM);

    gatherX<<<SS * BB / 8, 256>>>(enc_emb, src, SS, 0);
    splitWih<<<H3 / 8, 256>>>(enc_Wih, EE, 0);
    gi_mma<<<dim3(SS * BB / GBM, H3 / GBN), 256, MM_SMEM>>>(enc_bih, 0);
    enc_scan<<<NCTA, 512>>>(enc_Whh, enc_bhh);
    gatherX<<<TT * BB / 8, 256>>>(dec_emb, tgt, TT, 1);
    splitWih<<<H3 / 8, 256>>>(dec_Wih, EE + HH, 1);
    gi_mma<<<dim3(TT * BB / GBM, H3 / GBN), 256, MM_SMEM>>>(dec_bih, 1);
    dec_scan<<<NCTA, 512, DEC_WSMEM>>>(dec_Whh, dec_bhh, dec_Wih, src);
    convA<<<512, 1024>>>();
    convW<<<(VV * 256) / 1024, 1024>>>(fc_W);
    fc_mma<<<dim3(TT * BB / GBM, VV / FCBN), 256, FC_SMEM3>>>(fc_b, out);
}

// round 16
// speedup vs baseline: 1.0872x; 1.0760x over previous
#include <cuda_runtime.h>
#include <cuda_bf16.h>
#include <cuda_fp16.h>
#include <cstdint>

// Problem constants
#define BB 32
#define SS 256
#define TT 64
#define EE 256
#define HH 512
#define VV 32000
#define H3 1536

// GEMM tile config (both gi and fc): 128x128 tile, 256 thr, BK=64, 3-stage
#define GBM 128
#define GBN 128
#define GBK 64
#define GLDA 72                 // padded row (16-bit elems)
#define GBUF_B (GBM * GLDA * 2) // 18432 bytes per stage buffer
#define MM_SMEM (6 * GBUF_B)    // 110592 (3 stages x (A+B))

// fc K layout: A = fp16 hi only (K=1024); W = fp16 [hi|lo] (K=2048)
#define FCKA 1024
#define FCKB 2048
#define FC_NC 32                // 2 segments x 16 chunks
// gi K layout: bf16 [hi|lo] (K=512), 3 logical segments
#define GIX 512
#define GI_NC 12

#define NCTA 128
#define DEC_WSMEM 49152

// ---------------- scratch ----------------
__device__ float g_enc_gi[SS * H3 * BB];
__device__ float g_dec_gie[TT * H3 * BB];
__device__ float g_eo[SS * HH * BB];
__device__ float g_h0[HH * BB];          // never written -> stays zero
__device__ float g_hdec[2][HH * BB];
__device__ float g_ctx[HH * BB];
__device__ float g_scores[SS * BB];
__device__ float g_pred[(TT * BB) * (2 * HH)];
__device__ __half g_Wb[(size_t)VV * FCKB];        // fp16 [hi|lo] 131MB
__device__ __half g_Ab[(size_t)(TT * BB) * FCKA]; // fp16 hi
__device__ __nv_bfloat16 g_Xe[(size_t)(SS * BB) * GIX];
__device__ __nv_bfloat16 g_Xd[(size_t)(TT * BB) * GIX];
__device__ __nv_bfloat16 g_We[(size_t)H3 * GIX];
__device__ __nv_bfloat16 g_Wd[(size_t)H3 * GIX];
__device__ unsigned g_bar_cnt;
__device__ unsigned g_bar_gen;

// ---------------- grid barrier (proven) ----------------
__device__ __forceinline__ void grid_sync(unsigned nb) {
    __syncthreads();
    if (threadIdx.x == 0) {
        __threadfence();
        volatile unsigned* genp = &g_bar_gen;
        unsigned gen = *genp;
        if (atomicAdd(&g_bar_cnt, 1u) == nb - 1u) {
            g_bar_cnt = 0;
            __threadfence();
            *genp = gen + 1u;
        } else {
            while (*genp == gen) { }
            __threadfence();
        }
    }
    __syncthreads();
}

__device__ __forceinline__ float sigm(float x) { return 1.0f / (1.0f + __expf(-x)); }

__device__ __forceinline__ uint32_t smem_u32(const void* p) {
    uint32_t a;
    asm("{ .reg .u64 t; cvta.to.shared.u64 t, %1; cvt.u32.u64 %0, t; }" : "=r"(a) : "l"(p));
    return a;
}
__device__ __forceinline__ void cpasync16(uint32_t dst, const void* src) {
    asm volatile("cp.async.cg.shared.global [%0], [%1], 16;" :: "r"(dst), "l"(src) : "memory");
}
#define LDSM4(r0, r1, r2, r3, addr) \
    asm volatile("ldmatrix.sync.aligned.m8n8.x4.shared.b16 {%0,%1,%2,%3}, [%4];" \
                 : "=r"(r0), "=r"(r1), "=r"(r2), "=r"(r3) : "r"(addr))
#define MMA16816(c, a, b0, b1) \
    asm volatile("mma.sync.aligned.m16n8k16.row.col.f32.bf16.bf16.f32 " \
                 "{%0,%1,%2,%3}, {%4,%5,%6,%7}, {%8,%9}, {%0,%1,%2,%3};" \
                 : "+f"((c)[0]), "+f"((c)[1]), "+f"((c)[2]), "+f"((c)[3]) \
                 : "r"((a)[0]), "r"((a)[1]), "r"((a)[2]), "r"((a)[3]), "r"(b0), "r"(b1))
#define MMA16816H(c, a, b0, b1) \
    asm volatile("mma.sync.aligned.m16n8k16.row.col.f32.f16.f16.f32 " \
                 "{%0,%1,%2,%3}, {%4,%5,%6,%7}, {%8,%9}, {%0,%1,%2,%3};" \
                 : "+f"((c)[0]), "+f"((c)[1]), "+f"((c)[2]), "+f"((c)[3]) \
                 : "r"((a)[0]), "r"((a)[1]), "r"((a)[2]), "r"((a)[3]), "r"(b0), "r"(b1))

__device__ __forceinline__ void split4(float4 v, __nv_bfloat162& hA, __nv_bfloat162& hB,
                                       __nv_bfloat162& lA, __nv_bfloat162& lB) {
    __nv_bfloat16 h0 = __float2bfloat16(v.x), h1 = __float2bfloat16(v.y);
    __nv_bfloat16 h2 = __float2bfloat16(v.z), h3 = __float2bfloat16(v.w);
    __nv_bfloat16 l0 = __float2bfloat16(v.x - __bfloat162float(h0));
    __nv_bfloat16 l1 = __float2bfloat16(v.y - __bfloat162float(h1));
    __nv_bfloat16 l2 = __float2bfloat16(v.z - __bfloat162float(h2));
    __nv_bfloat16 l3 = __float2bfloat16(v.w - __bfloat162float(h3));
    hA = {h0, h1}; hB = {h2, h3}; lA = {l0, l1}; lB = {l2, l3};
}
__device__ __forceinline__ void split4h(float4 v, __half2& hA, __half2& hB,
                                        __half2& lA, __half2& lB) {
    __half h0 = __float2half_rn(v.x), h1 = __float2half_rn(v.y);
    __half h2 = __float2half_rn(v.z), h3 = __float2half_rn(v.w);
    __half l0 = __float2half_rn(v.x - __half2float(h0));
    __half l1 = __float2half_rn(v.y - __half2float(h1));
    __half l2 = __float2half_rn(v.z - __half2float(h2));
    __half l3 = __float2half_rn(v.w - __half2float(h3));
    hA = {h0, h1}; hB = {h2, h3}; lA = {l0, l1}; lB = {l2, l3};
}

// ---------------- W split (fp16): g_Wb[n] = [hi(1024) | lo(1024)]
__global__ void convW(const float* __restrict__ W) {
    size_t i = (size_t)blockIdx.x * 1024 + threadIdx.x;
    float4 v = ((const float4*)W)[i];
    size_t n = i >> 8;
    size_t k4 = (i & 255) * 4;
    __half2 hA, hB, lA, lB;
    split4h(v, hA, hB, lA, lB);
    __half* dst = g_Wb + n * FCKB;
    *(__half2*)(dst + k4) = hA;          *(__half2*)(dst + k4 + 2) = hB;
    *(__half2*)(dst + 1024 + k4) = lA;   *(__half2*)(dst + 1024 + k4 + 2) = lB;
}

// ---------------- pred conv (fp16 hi only): g_Ab[m][k] = fp16(pred)
__global__ void convA() {
    size_t i = (size_t)blockIdx.x * 1024 + threadIdx.x;
    float4 v = ((const float4*)g_pred)[i];
    size_t m = i >> 8;
    size_t k4 = (i & 255) * 4;
    __half2 a = {__float2half_rn(v.x), __float2half_rn(v.y)};
    __half2 b = {__float2half_rn(v.z), __float2half_rn(v.w)};
    __half* dst = g_Ab + m * FCKA;
    *(__half2*)(dst + k4) = a;
    *(__half2*)(dst + k4 + 2) = b;
}

// ---------------- gather embedding rows + split (bf16 [hi|lo])
__global__ void gatherX(const float* __restrict__ emb, const int* __restrict__ tok,
                        int L, int which) {
    __nv_bfloat16* X = which ? g_Xd : g_Xe;
    int m = blockIdx.x * 8 + (threadIdx.x >> 5);
    int lane = threadIdx.x & 31;
    int t = m >> 5, b = m & 31;
    int tv = tok[b * L + t];
    const float4* er = (const float4*)(emb + (size_t)tv * EE);
    __nv_bfloat16* dst = X + (size_t)m * GIX;
    #pragma unroll
    for (int q = 0; q < 2; q++) {
        float4 v = er[lane * 2 + q];
        int e = lane * 8 + q * 4;
        __nv_bfloat162 hA, hB, lA, lB;
        split4(v, hA, hB, lA, lB);
        *(__nv_bfloat162*)(dst + e) = hA;            *(__nv_bfloat162*)(dst + e + 2) = hB;
        *(__nv_bfloat162*)(dst + 256 + e) = lA;      *(__nv_bfloat162*)(dst + 256 + e + 2) = lB;
    }
}

// ---------------- split Wih rows (first 256 cols), bf16 [hi|lo]
__global__ void splitWih(const float* __restrict__ W, int stride, int which) {
    __nv_bfloat16* out = which ? g_Wd : g_We;
    int j = blockIdx.x * 8 + (threadIdx.x >> 5);
    int lane = threadIdx.x & 31;
    const float4* wr = (const float4*)(W + (size_t)j * stride);
    __nv_bfloat16* dst = out + (size_t)j * GIX;
    #pragma unroll
    for (int q = 0; q < 2; q++) {
        float4 v = wr[lane * 2 + q];
        int e = lane * 8 + q * 4;
        __nv_bfloat162 hA, hB, lA, lB;
        split4(v, hA, hB, lA, lB);
        *(__nv_bfloat162*)(dst + e) = hA;            *(__nv_bfloat162*)(dst + e + 2) = hB;
        *(__nv_bfloat162*)(dst + 256 + e) = lA;      *(__nv_bfloat162*)(dst + 256 + e + 2) = lB;
    }
}

// ---------------- gi GEMM via HMMA bf16 (256 thr, 128x128, 3 segments K eff 768)
__global__ void __launch_bounds__(256) gi_mma(const float* __restrict__ bih, int which) {
    extern __shared__ uint8_t dynsmem[];
    uint32_t sA = smem_u32(dynsmem);
    uint32_t sB = sA + 3 * GBUF_B;

    const __nv_bfloat16* A = which ? g_Xd : g_Xe;
    const __nv_bfloat16* Bm = which ? g_Wd : g_We;
    float* outg = which ? g_dec_gie : g_enc_gi;

    int tid = threadIdx.x;
    int wid = tid >> 5, lane = tid & 31;
    int wm = wid & 3, wn = wid >> 2;
    int m0 = blockIdx.x * GBM;
    int n0 = blockIdx.y * GBN;

    const char* Ag = (const char*)(A + (size_t)m0 * GIX);
    const char* Bg = (const char*)(Bm + (size_t)n0 * GIX);
    int lrow = tid >> 3, lu = tid & 7;

    auto load_chunk = [&](int kc, int st) {
        int seg = kc >> 2, c = kc & 3;
        size_t aoff = (size_t)(((seg == 2) ? 256 : 0) + c * 64) * 2;
        size_t boff = (size_t)(((seg == 1) ? 256 : 0) + c * 64) * 2;
        uint32_t sa = sA + st * GBUF_B;
        uint32_t sbm = sB + st * GBUF_B;
        #pragma unroll
        for (int it = 0; it < 4; it++) {
            int row = it * 32 + lrow;
            uint32_t doff = (uint32_t)(row * (GLDA * 2) + lu * 16);
            cpasync16(sa + doff, Ag + (size_t)row * (GIX * 2) + aoff + lu * 16);
            cpasync16(sbm + doff, Bg + (size_t)row * (GIX * 2) + boff + lu * 16);
        }
        asm volatile("cp.async.commit_group;" ::: "memory");
    };

    float acc[2][8][4];
    #pragma unroll
    for (int a = 0; a < 2; a++)
        #pragma unroll
        for (int b = 0; b < 8; b++)
            #pragma unroll
            for (int c = 0; c < 4; c++) acc[a][b][c] = 0.0f;

    uint32_t aBase = (uint32_t)(((wm * 32 + (lane & 15)) * GLDA + (lane >> 4) * 8) * 2);
    uint32_t bBase = (uint32_t)(((wn * 64 + (lane & 7) + ((lane >> 4) & 1) * 8) * GLDA
                                 + ((lane >> 3) & 1) * 8) * 2);

    load_chunk(0, 0);
    load_chunk(1, 1);
    for (int kc = 0; kc < GI_NC; kc++) {
        int st = kc % 3;
        if (kc == GI_NC - 1) { asm volatile("cp.async.wait_group 0;" ::: "memory"); }
        else                 { asm volatile("cp.async.wait_group 1;" ::: "memory"); }
        __syncthreads();
        if (kc + 2 < GI_NC) load_chunk(kc + 2, (kc + 2) % 3);
        uint32_t sa = sA + st * GBUF_B + aBase;
        uint32_t sbm = sB + st * GBUF_B + bBase;
        #pragma unroll
        for (int ks = 0; ks < 4; ks++) {
            uint32_t koff = (uint32_t)(ks * 16 * 2);
            uint32_t a0[4], a1[4];
            LDSM4(a0[0], a0[1], a0[2], a0[3], sa + koff);
            LDSM4(a1[0], a1[1], a1[2], a1[3], sa + 16 * GLDA * 2 + koff);
            uint32_t bf[16];
            #pragma unroll
            for (int nt = 0; nt < 4; nt++)
                LDSM4(bf[nt * 4 + 0], bf[nt * 4 + 1], bf[nt * 4 + 2], bf[nt * 4 + 3],
                      sbm + nt * 16 * GLDA * 2 + koff);
            #pragma unroll
            for (int j = 0; j < 8; j++) {
                int nt = j >> 1, hf = j & 1;
                MMA16816(acc[0][j], a0, bf[nt * 4 + hf * 2], bf[nt * 4 + hf * 2 + 1]);
                MMA16816(acc[1][j], a1, bf[nt * 4 + hf * 2], bf[nt * 4 + hf * 2 + 1]);
            }
        }
    }
    __syncthreads();

    #pragma unroll
    for (int mt = 0; mt < 2; mt++) {
        #pragma unroll
        for (int half = 0; half < 2; half++) {
            int m = m0 + wm * 32 + mt * 16 + (lane >> 2) + half * 8;
            int t = m >> 5, b = m & 31;
            float* obase = outg + (size_t)t * (H3 * BB) + b;
            #pragma unroll
            for (int j = 0; j < 8; j++) {
                int n = n0 + wn * 64 + j * 8 + (lane & 3) * 2;
                obase[(size_t)n * 32] = acc[mt][j][half * 2 + 0] + __ldg(bih + n);
                obase[(size_t)(n + 1) * 32] = acc[mt][j][half * 2 + 1] + __ldg(bih + n + 1);
            }
        }
    }
}

// ---------------- encoder scan (weights in SMEM, gi prefetched) ----------------
__global__ void __launch_bounds__(512) enc_scan(const float* __restrict__ Whh,
                                                const float* __restrict__ bhh) {
    int wid = threadIdx.x >> 5, lane = threadIdx.x & 31;
    int iLocal = wid & 3;
    int kq = wid >> 2;
    int i = blockIdx.x * 4 + iLocal;
    __shared__ float sW[16][3][128];
    __shared__ float ps[4][3][3][32];
    __shared__ float sgi[2][12][32];
    __shared__ float sbh[12];

    #pragma unroll
    for (int g = 0; g < 3; g++) {
        float4 w = *(const float4*)(Whh + ((size_t)g * HH + i) * HH + kq * 128 + lane * 4);
        *(float4*)&sW[wid][g][lane * 4] = w;
    }
    if (threadIdx.x < 12) {
        int g = threadIdx.x >> 2, il = threadIdx.x & 3;
        sbh[threadIdx.x] = bhh[g * HH + blockIdx.x * 4 + il];
    }

    auto prefetch_gi = [&](int t, int buf) {
        if (threadIdx.x < 96) {
            int row = threadIdx.x >> 3, u = threadIdx.x & 7;
            int g = row >> 2, il = row & 3;
            const float* src = g_enc_gi + (size_t)t * (H3 * BB)
                             + ((size_t)g * HH + blockIdx.x * 4 + il) * 32 + u * 4;
            cpasync16(smem_u32(&sgi[buf][row][u * 4]), src);
        }
        asm volatile("cp.async.commit_group;" ::: "memory");
    };
    prefetch_gi(0, 0);
    __syncthreads();

    for (int t = 0; t < SS; t++) {
        if (t + 1 < SS) prefetch_gi(t + 1, (t + 1) & 1);
        const float* hprev = t ? (g_eo + (t - 1) * (HH * BB)) : g_h0;
        const float* hp = hprev + kq * 128 * 32 + lane;
        float s0 = 0, s1 = 0, s2 = 0;
        #pragma unroll 8
        for (int q = 0; q < 32; q++) {
            float h0 = hp[q * 128 + 0];
            float h1 = hp[q * 128 + 32];
            float h2 = hp[q * 128 + 64];
            float h3 = hp[q * 128 + 96];
            float4 w0 = *(const float4*)&sW[wid][0][q * 4];
            float4 w1 = *(const float4*)&sW[wid][1][q * 4];
            float4 w2 = *(const float4*)&sW[wid][2][q * 4];
            s0 += w0.x * h0 + w0.y * h1 + w0.z * h2 + w0.w * h3;
            s1 += w1.x * h0 + w1.y * h1 + w1.z * h2 + w1.w * h3;
            s2 += w2.x * h0 + w2.y * h1 + w2.z * h2 + w2.w * h3;
        }
        if (kq > 0) {
            ps[iLocal][kq - 1][0][lane] = s0;
            ps[iLocal][kq - 1][1][lane] = s1;
            ps[iLocal][kq - 1][2][lane] = s2;
        }
        asm volatile("cp.async.wait_group 1;" ::: "memory");
        __syncthreads();
        if (wid < 4) {
            float rh = s0 + ps[wid][0][0][lane] + ps[wid][1][0][lane] + ps[wid][2][0][lane] + sbh[wid];
            float zh = s1 + ps[wid][0][1][lane] + ps[wid][1][1][lane] + ps[wid][2][1][lane] + sbh[4 + wid];
            float nh = s2 + ps[wid][0][2][lane] + ps[wid][1][2][lane] + ps[wid][2][2][lane] + sbh[8 + wid];
            float ir = sgi[t & 1][wid][lane];
            float iz = sgi[t & 1][4 + wid][lane];
            float in_ = sgi[t & 1][8 + wid][lane];
            float r = sigm(ir + rh);
            float z = sigm(iz + zh);
            float n = tanhf(in_ + r * nh);
            int ii = blockIdx.x * 4 + wid;
            float hv = hprev[ii * 32 + lane];
            g_eo[t * (HH * BB) + ii * 32 + lane] = (1.0f - z) * n + z * hv;
        }
        grid_sync(gridDim.x);
    }
}

// ---------------- decoder scan (phase-D weights in dynamic SMEM, gie prefetched)
__global__ void __launch_bounds__(512) dec_scan(const float* __restrict__ Whh,
                                                const float* __restrict__ bhh,
                                                const float* __restrict__ Wih,
                                                const int* __restrict__ src) {
    extern __shared__ float sWD[];
    int wid = threadIdx.x >> 5, lane = threadIdx.x & 31;
    int iLocal = wid & 3;
    int kqD = wid >> 2;
    int iD = blockIdx.x * 4 + iLocal;
    __shared__ float psA[2][8][32];
    __shared__ float psC[4][4][32];
    __shared__ float denS[32];
    __shared__ float psD[4][3][6][32];
    __shared__ float sgie[12][32];
    __shared__ float sbh[12];

    float* wrow = sWD + wid * 6 * 128;
    #pragma unroll
    for (int g = 0; g < 3; g++) {
        *(float4*)&wrow[g * 128 + lane * 4] =
            *(const float4*)(Whh + ((size_t)g * HH + iD) * HH + kqD * 128 + lane * 4);
        *(float4*)&wrow[(3 + g) * 128 + lane * 4] =
            *(const float4*)(Wih + ((size_t)g * HH + iD) * 768 + EE + kqD * 128 + lane * 4);
    }
    if (threadIdx.x < 12) {
        int g = threadIdx.x >> 2, il = threadIdx.x & 3;
        sbh[threadIdx.x] = bhh[g * HH + blockIdx.x * 4 + il];
    }
    __syncthreads();

    for (int t = 0; t < TT; t++) {
        if (threadIdx.x < 96) {
            int row = threadIdx.x >> 3, u = threadIdx.x & 7;
            int g = row >> 2, il = row & 3;
            const float* srcp = g_dec_gie + (size_t)t * (H3 * BB)
                              + ((size_t)g * HH + blockIdx.x * 4 + il) * 32 + u * 4;
            cpasync16(smem_u32(&sgie[row][u * 4]), srcp);
        }
        asm volatile("cp.async.commit_group;" ::: "memory");

        const float* h = t ? g_hdec[t & 1] : (g_eo + (SS - 1) * (HH * BB));
        {
            int s = blockIdx.x * 2 + (wid & 1);
            int kq8 = wid >> 1;
            float acc = 0.0f;
            const float* eo = g_eo + s * (HH * BB) + kq8 * 64 * 32 + lane;
            const float* hp = h + kq8 * 64 * 32 + lane;
            #pragma unroll 8
            for (int k = 0; k < 64; k++) acc += eo[k * 32] * hp[k * 32];
            psA[wid & 1][kq8][lane] = acc;
            __syncthreads();
            if (wid < 2) {
                int ss2 = blockIdx.x * 2 + wid;
                float sc = 0.0f;
                #pragma unroll
                for (int q = 0; q < 8; q++) sc += psA[wid][q][lane];
                int tokv = src[lane * SS + ss2];
                float e = (tokv == 0) ? 0.0f : __expf(sc);
                g_scores[ss2 * 32 + lane] = e;
            }
        }
        grid_sync(gridDim.x);
        {
            int k = blockIdx.x * 4 + (wid & 3);
            int sq = wid >> 2;
            float acc = 0.0f;
            const float* eo = g_eo + sq * 64 * (HH * BB) + k * 32 + lane;
            const float* sce = g_scores + sq * 64 * 32 + lane;
            #pragma unroll 8
            for (int s = 0; s < 64; s++) acc += sce[s * 32] * eo[s * (HH * BB)];
            psC[wid & 3][sq][lane] = acc;
            if (wid == 0) {
                float d = 0.0f;
                const float* sp = g_scores + lane;
                #pragma unroll 8
                for (int s = 0; s < SS; s++) d += sp[s * 32];
                denS[lane] = d;
            }
            __syncthreads();
            if (wid < 4) {
                int kk = blockIdx.x * 4 + wid;
                float c = (psC[wid][0][lane] + psC[wid][1][lane] + psC[wid][2][lane] + psC[wid][3][lane])
                          / denS[lane];
                g_ctx[kk * 32 + lane] = c;
                g_pred[(t * 32 + lane) * (2 * HH) + HH + kk] = c;
            }
        }
        grid_sync(gridDim.x);
        {
            float a0 = 0, a1 = 0, a2 = 0, c0 = 0, c1 = 0, c2 = 0;
            {
                const float* hp = h + kqD * 128 * 32 + lane;
                const float* cp = g_ctx + kqD * 128 * 32 + lane;
                #pragma unroll 4
                for (int q = 0; q < 32; q++) {
                    float h0 = hp[q * 128 + 0], h1 = hp[q * 128 + 32];
                    float h2 = hp[q * 128 + 64], h3 = hp[q * 128 + 96];
                    float x0 = cp[q * 128 + 0], x1 = cp[q * 128 + 32];
                    float x2 = cp[q * 128 + 64], x3 = cp[q * 128 + 96];
                    float4 w;
                    w = *(const float4*)&wrow[0 * 128 + q * 4];
                    a0 += w.x * h0 + w.y * h1 + w.z * h2 + w.w * h3;
                    w = *(const float4*)&wrow[1 * 128 + q * 4];
                    a1 += w.x * h0 + w.y * h1 + w.z * h2 + w.w * h3;
                    w = *(const float4*)&wrow[2 * 128 + q * 4];
                    a2 += w.x * h0 + w.y * h1 + w.z * h2 + w.w * h3;
                    w = *(const float4*)&wrow[3 * 128 + q * 4];
                    c0 += w.x * x0 + w.y * x1 + w.z * x2 + w.w * x3;
                    w = *(const float4*)&wrow[4 * 128 + q * 4];
                    c1 += w.x * x0 + w.y * x1 + w.z * x2 + w.w * x3;
                    w = *(const float4*)&wrow[5 * 128 + q * 4];
                    c2 += w.x * x0 + w.y * x1 + w.z * x2 + w.w * x3;
                }
            }
            if (kqD > 0) {
                psD[iLocal][kqD - 1][0][lane] = a0;
                psD[iLocal][kqD - 1][1][lane] = a1;
                psD[iLocal][kqD - 1][2][lane] = a2;
                psD[iLocal][kqD - 1][3][lane] = c0;
                psD[iLocal][kqD - 1][4][lane] = c1;
                psD[iLocal][kqD - 1][5][lane] = c2;
            }
            asm volatile("cp.async.wait_group 0;" ::: "memory");
            __syncthreads();
            if (wid < 4) {
                float rh = a0, zh = a1, nh = a2, rc = c0, zc = c1, nc = c2;
                #pragma unroll
                for (int kk = 0; kk < 3; kk++) {
                    rh += psD[wid][kk][0][lane];
                    zh += psD[wid][kk][1][lane];
                    nh += psD[wid][kk][2][lane];
                    rc += psD[wid][kk][3][lane];
                    zc += psD[wid][kk][4][lane];
                    nc += psD[wid][kk][5][lane];
                }
                rh += sbh[wid]; zh += sbh[4 + wid]; nh += sbh[8 + wid];
                float ir = sgie[wid][lane] + rc;
                float iz = sgie[4 + wid][lane] + zc;
                float in_ = sgie[8 + wid][lane] + nc;
                float r = sigm(ir + rh);
                float z = sigm(iz + zh);
                float n = tanhf(in_ + r * nh);
                int ii = blockIdx.x * 4 + wid;
                float hold = h[ii * 32 + lane];
                float hn = (1.0f - z) * n + z * hold;
                g_hdec[(t + 1) & 1][ii * 32 + lane] = hn;
                g_pred[(t * 32 + lane) * (2 * HH) + ii] = hn;
            }
        }
        grid_sync(gridDim.x);
    }
}

// ---------------- fc GEMM via mma.sync fp16 (256 thr, 128x128, 2 segments)
__global__ void __launch_bounds__(256) fc_mma(const float* __restrict__ bias,
                                              float* __restrict__ out) {
    extern __shared__ uint8_t dynsmem[];
    uint32_t sA = smem_u32(dynsmem);           // 3 stages
    uint32_t sB = sA + 3 * GBUF_B;

    int tid = threadIdx.x;
    int wid = tid >> 5, lane = tid & 31;
    int wm = wid & 3, wn = wid >> 2;
    int m0 = blockIdx.x * GBM;
    int n0 = blockIdx.y * GBN;

    const char* Ag = (const char*)(g_Ab + (size_t)m0 * FCKA);
    const char* Bg = (const char*)(g_Wb + (size_t)n0 * FCKB);
    int lrow = tid >> 3, lu = tid & 7;

    auto load_chunk = [&](int kc, int st) {
        int seg = kc >> 4, c = kc & 15;
        size_t aoff = (size_t)(c * 64) * 2;                       // A always hi
        size_t boff = (size_t)((seg ? 1024 : 0) + c * 64) * 2;    // B hi or lo
        uint32_t sa = sA + st * GBUF_B;
        uint32_t sbm = sB + st * GBUF_B;
        #pragma unroll
        for (int it = 0; it < 4; it++) {
            int row = it * 32 + lrow;
            uint32_t doff = (uint32_t)(row * (GLDA * 2) + lu * 16);
            cpasync16(sa + doff, Ag + (size_t)row * (FCKA * 2) + aoff + lu * 16);
            cpasync16(sbm + doff, Bg + (size_t)row * (FCKB * 2) + boff + lu * 16);
        }
        asm volatile("cp.async.commit_group;" ::: "memory");
    };

    float acc[2][8][4];
    #pragma unroll
    for (int a = 0; a < 2; a++)
        #pragma unroll
        for (int b = 0; b < 8; b++)
            #pragma unroll
            for (int c = 0; c < 4; c++) acc[a][b][c] = 0.0f;

    uint32_t aBase = (uint32_t)(((wm * 32 + (lane & 15)) * GLDA + (lane >> 4) * 8) * 2);
    uint32_t bBase = (uint32_t)(((wn * 64 + (lane & 7) + ((lane >> 4) & 1) * 8) * GLDA
                                 + ((lane >> 3) & 1) * 8) * 2);

    load_chunk(0, 0);
    load_chunk(1, 1);
    for (int kc = 0; kc < FC_NC; kc++) {
        int st = kc % 3;
        if (kc == FC_NC - 1) { asm volatile("cp.async.wait_group 0;" ::: "memory"); }
        else                 { asm volatile("cp.async.wait_group 1;" ::: "memory"); }
        __syncthreads();
        if (kc + 2 < FC_NC) load_chunk(kc + 2, (kc + 2) % 3);
        uint32_t sa = sA + st * GBUF_B + aBase;
        uint32_t sbm = sB + st * GBUF_B + bBase;
        #pragma unroll
        for (int ks = 0; ks < 4; ks++) {
            uint32_t koff = (uint32_t)(ks * 16 * 2);
            uint32_t a0[4], a1[4];
            LDSM4(a0[0], a0[1], a0[2], a0[3], sa + koff);
            LDSM4(a1[0], a1[1], a1[2], a1[3], sa + 16 * GLDA * 2 + koff);
            uint32_t bf[16];
            #pragma unroll
            for (int nt = 0; nt < 4; nt++)
                LDSM4(bf[nt * 4 + 0], bf[nt * 4 + 1], bf[nt * 4 + 2], bf[nt * 4 + 3],
                      sbm + nt * 16 * GLDA * 2 + koff);
            #pragma unroll
            for (int j = 0; j < 8; j++) {
                int nt = j >> 1, hf = j & 1;
                MMA16816H(acc[0][j], a0, bf[nt * 4 + hf * 2], bf[nt * 4 + hf * 2 + 1]);
                MMA16816H(acc[1][j], a1, bf[nt * 4 + hf * 2], bf[nt * 4 + hf * 2 + 1]);
            }
        }
    }
    __syncthreads();

    float bv[8][2];
    #pragma unroll
    for (int j = 0; j < 8; j++) {
        int n = n0 + wn * 64 + j * 8 + (lane & 3) * 2;
        bv[j][0] = __ldg(bias + n);
        bv[j][1] = __ldg(bias + n + 1);
    }
    #pragma unroll
    for (int mt = 0; mt < 2; mt++) {
        #pragma unroll
        for (int half = 0; half < 2; half++) {
            int m = m0 + wm * 32 + mt * 16 + (lane >> 2) + half * 8;
            int t = m >> 5, b = m & 31;
            float* orow = out + (size_t)b * (TT * VV) + (size_t)t * VV;
            #pragma unroll
            for (int j = 0; j < 8; j++) {
                int n = n0 + wn * 64 + j * 8 + (lane & 3) * 2;
                float2 v;
                v.x = acc[mt][j][half * 2 + 0] + bv[j][0];
                v.y = acc[mt][j][half * 2 + 1] + bv[j][1];
                *(float2*)(orow + n) = v;
            }
        }
    }
}

// ---------------- launch (serial, proven order) ----------------
extern "C" void kernel_launch(void* const* d_in, const int* in_sizes, int n_in,
                              void* d_out, int out_size) {
    const int* src = (const int*)d_in[0];
    const int* tgt = (const int*)d_in[2];
    const float* enc_emb = (const float*)d_in[3];
    const float* enc_Wih = (const float*)d_in[4];
    const float* enc_Whh = (const float*)d_in[5];
    const float* enc_bih = (const float*)d_in[6];
    const float* enc_bhh = (const float*)d_in[7];
    const float* dec_emb = (const float*)d_in[8];
    const float* dec_Wih = (const float*)d_in[9];
    const float* dec_Whh = (const float*)d_in[10];
    const float* dec_bih = (const float*)d_in[11];
    const float* dec_bhh = (const float*)d_in[12];
    const float* fc_W = (const float*)d_in[13];
    const float* fc_b = (const float*)d_in[14];
    float* out = (float*)d_out;

    cudaFuncSetAttribute(fc_mma, cudaFuncAttributeMaxDynamicSharedMemorySize, MM_SMEM);
    cudaFuncSetAttribute(gi_mma, cudaFuncAttributeMaxDynamicSharedMemorySize, MM_SMEM);
    cudaFuncSetAttribute(dec_scan, cudaFuncAttributeMaxDynamicSharedMemorySize, DEC_WSMEM);

    gatherX<<<SS * BB / 8, 256>>>(enc_emb, src, SS, 0);
    splitWih<<<H3 / 8, 256>>>(enc_Wih, EE, 0);
    gi_mma<<<dim3(SS * BB / GBM, H3 / GBN), 256, MM_SMEM>>>(enc_bih, 0);
    enc_scan<<<NCTA, 512>>>(enc_Whh, enc_bhh);
    gatherX<<<TT * BB / 8, 256>>>(dec_emb, tgt, TT, 1);
    splitWih<<<H3 / 8, 256>>>(dec_Wih, EE + HH, 1);
    gi_mma<<<dim3(TT * BB / GBM, H3 / GBN), 256, MM_SMEM>>>(dec_bih, 1);
    dec_scan<<<NCTA, 512, DEC_WSMEM>>>(dec_Whh, dec_bhh, dec_Wih, src);
    convA<<<512, 1024>>>();
    convW<<<(VV * 256) / 1024, 1024>>>(fc_W);
    fc_mma<<<dim3(TT * BB / GBM, VV / GBN), 256, MM_SMEM>>>(fc_b, out);
}

// round 17
// speedup vs baseline: 1.0882x; 1.0010x over previous
#include <cuda_runtime.h>
#include <cuda_bf16.h>
#include <cuda_fp16.h>
#include <cstdint>

// Problem constants
#define BB 32
#define SS 256
#define TT 64
#define EE 256
#define HH 512
#define VV 32000
#define H3 1536

// GEMM tile config (both gi and fc): 128x128 tile, 256 thr, BK=64, 3-stage
#define GBM 128
#define GBN 128
#define GBK 64
#define GLDA 72                 // padded row (16-bit elems)
#define GBUF_B (GBM * GLDA * 2) // 18432 bytes per stage buffer
#define MM_SMEM (6 * GBUF_B)    // 110592 (3 stages x (A+B))

// fc K layout: A = fp16 hi only (K=1024); W = fp16 [hi|lo] (K=2048)
#define FCKA 1024
#define FCKB 2048
#define FC_NC 32                // 2 segments x 16 chunks
// gi K layout: bf16 [hi|lo] (K=512), 3 logical segments
#define GIX 512
#define GI_NC 12

#define NCTA 128
#define DEC_WSMEM 49152

// ---------------- scratch ----------------
__device__ float g_enc_gi[SS * H3 * BB];
__device__ float g_dec_gie[TT * H3 * BB];
__device__ float g_eo[SS * HH * BB];
__device__ float g_h0[HH * BB];          // never written -> stays zero
__device__ float g_hdec[2][HH * BB];
__device__ float g_ctx[HH * BB];
__device__ float g_scores[SS * BB];
__device__ float g_pred[(TT * BB) * (2 * HH)];
__device__ __half g_Wb[(size_t)VV * FCKB];        // fp16 [hi|lo] 131MB
__device__ __half g_Ab[(size_t)(TT * BB) * FCKA]; // fp16 hi
__device__ __nv_bfloat16 g_Xe[(size_t)(SS * BB) * GIX];
__device__ __nv_bfloat16 g_Xd[(size_t)(TT * BB) * GIX];
__device__ __nv_bfloat16 g_We[(size_t)H3 * GIX];
__device__ __nv_bfloat16 g_Wd[(size_t)H3 * GIX];
// Barrier words on SEPARATE 128B L2 lines (poll storm on gen must not
// contend with arrival RMWs on cnt).
__device__ __align__(128) unsigned g_bar_cnt;
__device__ __align__(128) unsigned g_bar_gen;

// ---------------- grid barrier (R1 semantics + line split + poll backoff) ------
__device__ __forceinline__ void grid_sync(unsigned nb) {
    __syncthreads();
    if (threadIdx.x == 0) {
        __threadfence();
        volatile unsigned* genp = &g_bar_gen;
        unsigned gen = *genp;
        if (atomicAdd(&g_bar_cnt, 1u) == nb - 1u) {
            g_bar_cnt = 0;
            __threadfence();
            *genp = gen + 1u;
        } else {
            while (*genp == gen) { __nanosleep(32); }
            __threadfence();
        }
    }
    __syncthreads();
}

__device__ __forceinline__ float sigm(float x) { return 1.0f / (1.0f + __expf(-x)); }

__device__ __forceinline__ uint32_t smem_u32(const void* p) {
    uint32_t a;
    asm("{ .reg .u64 t; cvta.to.shared.u64 t, %1; cvt.u32.u64 %0, t; }" : "=r"(a) : "l"(p));
    return a;
}
__device__ __forceinline__ void cpasync16(uint32_t dst, const void* src) {
    asm volatile("cp.async.cg.shared.global [%0], [%1], 16;" :: "r"(dst), "l"(src) : "memory");
}
#define LDSM4(r0, r1, r2, r3, addr) \
    asm volatile("ldmatrix.sync.aligned.m8n8.x4.shared.b16 {%0,%1,%2,%3}, [%4];" \
                 : "=r"(r0), "=r"(r1), "=r"(r2), "=r"(r3) : "r"(addr))
#define MMA16816(c, a, b0, b1) \
    asm volatile("mma.sync.aligned.m16n8k16.row.col.f32.bf16.bf16.f32 " \
                 "{%0,%1,%2,%3}, {%4,%5,%6,%7}, {%8,%9}, {%0,%1,%2,%3};" \
                 : "+f"((c)[0]), "+f"((c)[1]), "+f"((c)[2]), "+f"((c)[3]) \
                 : "r"((a)[0]), "r"((a)[1]), "r"((a)[2]), "r"((a)[3]), "r"(b0), "r"(b1))
#define MMA16816H(c, a, b0, b1) \
    asm volatile("mma.sync.aligned.m16n8k16.row.col.f32.f16.f16.f32 " \
                 "{%0,%1,%2,%3}, {%4,%5,%6,%7}, {%8,%9}, {%0,%1,%2,%3};" \
                 : "+f"((c)[0]), "+f"((c)[1]), "+f"((c)[2]), "+f"((c)[3]) \
                 : "r"((a)[0]), "r"((a)[1]), "r"((a)[2]), "r"((a)[3]), "r"(b0), "r"(b1))

__device__ __forceinline__ void split4(float4 v, __nv_bfloat162& hA, __nv_bfloat162& hB,
                                       __nv_bfloat162& lA, __nv_bfloat162& lB) {
    __nv_bfloat16 h0 = __float2bfloat16(v.x), h1 = __float2bfloat16(v.y);
    __nv_bfloat16 h2 = __float2bfloat16(v.z), h3 = __float2bfloat16(v.w);
    __nv_bfloat16 l0 = __float2bfloat16(v.x - __bfloat162float(h0));
    __nv_bfloat16 l1 = __float2bfloat16(v.y - __bfloat162float(h1));
    __nv_bfloat16 l2 = __float2bfloat16(v.z - __bfloat162float(h2));
    __nv_bfloat16 l3 = __float2bfloat16(v.w - __bfloat162float(h3));
    hA = {h0, h1}; hB = {h2, h3}; lA = {l0, l1}; lB = {l2, l3};
}
__device__ __forceinline__ void split4h(float4 v, __half2& hA, __half2& hB,
                                        __half2& lA, __half2& lB) {
    __half h0 = __float2half_rn(v.x), h1 = __float2half_rn(v.y);
    __half h2 = __float2half_rn(v.z), h3 = __float2half_rn(v.w);
    __half l0 = __float2half_rn(v.x - __half2float(h0));
    __half l1 = __float2half_rn(v.y - __half2float(h1));
    __half l2 = __float2half_rn(v.z - __half2float(h2));
    __half l3 = __float2half_rn(v.w - __half2float(h3));
    hA = {h0, h1}; hB = {h2, h3}; lA = {l0, l1}; lB = {l2, l3};
}

// ---------------- W split (fp16): g_Wb[n] = [hi(1024) | lo(1024)]
__global__ void convW(const float* __restrict__ W) {
    size_t i = (size_t)blockIdx.x * 1024 + threadIdx.x;
    float4 v = ((const float4*)W)[i];
    size_t n = i >> 8;
    size_t k4 = (i & 255) * 4;
    __half2 hA, hB, lA, lB;
    split4h(v, hA, hB, lA, lB);
    __half* dst = g_Wb + n * FCKB;
    *(__half2*)(dst + k4) = hA;          *(__half2*)(dst + k4 + 2) = hB;
    *(__half2*)(dst + 1024 + k4) = lA;   *(__half2*)(dst + 1024 + k4 + 2) = lB;
}

// ---------------- pred conv (fp16 hi only)
__global__ void convA() {
    size_t i = (size_t)blockIdx.x * 1024 + threadIdx.x;
    float4 v = ((const float4*)g_pred)[i];
    size_t m = i >> 8;
    size_t k4 = (i & 255) * 4;
    __half2 a = {__float2half_rn(v.x), __float2half_rn(v.y)};
    __half2 b = {__float2half_rn(v.z), __float2half_rn(v.w)};
    __half* dst = g_Ab + m * FCKA;
    *(__half2*)(dst + k4) = a;
    *(__half2*)(dst + k4 + 2) = b;
}

// ---------------- gather embedding rows + split (bf16 [hi|lo])
__global__ void gatherX(const float* __restrict__ emb, const int* __restrict__ tok,
                        int L, int which) {
    __nv_bfloat16* X = which ? g_Xd : g_Xe;
    int m = blockIdx.x * 8 + (threadIdx.x >> 5);
    int lane = threadIdx.x & 31;
    int t = m >> 5, b = m & 31;
    int tv = tok[b * L + t];
    const float4* er = (const float4*)(emb + (size_t)tv * EE);
    __nv_bfloat16* dst = X + (size_t)m * GIX;
    #pragma unroll
    for (int q = 0; q < 2; q++) {
        float4 v = er[lane * 2 + q];
        int e = lane * 8 + q * 4;
        __nv_bfloat162 hA, hB, lA, lB;
        split4(v, hA, hB, lA, lB);
        *(__nv_bfloat162*)(dst + e) = hA;            *(__nv_bfloat162*)(dst + e + 2) = hB;
        *(__nv_bfloat162*)(dst + 256 + e) = lA;      *(__nv_bfloat162*)(dst + 256 + e + 2) = lB;
    }
}

// ---------------- split Wih rows (first 256 cols), bf16 [hi|lo]
__global__ void splitWih(const float* __restrict__ W, int stride, int which) {
    __nv_bfloat16* out = which ? g_Wd : g_We;
    int j = blockIdx.x * 8 + (threadIdx.x >> 5);
    int lane = threadIdx.x & 31;
    const float4* wr = (const float4*)(W + (size_t)j * stride);
    __nv_bfloat16* dst = out + (size_t)j * GIX;
    #pragma unroll
    for (int q = 0; q < 2; q++) {
        float4 v = wr[lane * 2 + q];
        int e = lane * 8 + q * 4;
        __nv_bfloat162 hA, hB, lA, lB;
        split4(v, hA, hB, lA, lB);
        *(__nv_bfloat162*)(dst + e) = hA;            *(__nv_bfloat162*)(dst + e + 2) = hB;
        *(__nv_bfloat162*)(dst + 256 + e) = lA;      *(__nv_bfloat162*)(dst + 256 + e + 2) = lB;
    }
}

// ---------------- gi GEMM via HMMA bf16 (256 thr, 128x128, 3 segments K eff 768)
__global__ void __launch_bounds__(256) gi_mma(const float* __restrict__ bih, int which) {
    extern __shared__ uint8_t dynsmem[];
    uint32_t sA = smem_u32(dynsmem);
    uint32_t sB = sA + 3 * GBUF_B;

    const __nv_bfloat16* A = which ? g_Xd : g_Xe;
    const __nv_bfloat16* Bm = which ? g_Wd : g_We;
    float* outg = which ? g_dec_gie : g_enc_gi;

    int tid = threadIdx.x;
    int wid = tid >> 5, lane = tid & 31;
    int wm = wid & 3, wn = wid >> 2;
    int m0 = blockIdx.x * GBM;
    int n0 = blockIdx.y * GBN;

    const char* Ag = (const char*)(A + (size_t)m0 * GIX);
    const char* Bg = (const char*)(Bm + (size_t)n0 * GIX);
    int lrow = tid >> 3, lu = tid & 7;

    auto load_chunk = [&](int kc, int st) {
        int seg = kc >> 2, c = kc & 3;
        size_t aoff = (size_t)(((seg == 2) ? 256 : 0) + c * 64) * 2;
        size_t boff = (size_t)(((seg == 1) ? 256 : 0) + c * 64) * 2;
        uint32_t sa = sA + st * GBUF_B;
        uint32_t sbm = sB + st * GBUF_B;
        #pragma unroll
        for (int it = 0; it < 4; it++) {
            int row = it * 32 + lrow;
            uint32_t doff = (uint32_t)(row * (GLDA * 2) + lu * 16);
            cpasync16(sa + doff, Ag + (size_t)row * (GIX * 2) + aoff + lu * 16);
            cpasync16(sbm + doff, Bg + (size_t)row * (GIX * 2) + boff + lu * 16);
        }
        asm volatile("cp.async.commit_group;" ::: "memory");
    };

    float acc[2][8][4];
    #pragma unroll
    for (int a = 0; a < 2; a++)
        #pragma unroll
        for (int b = 0; b < 8; b++)
            #pragma unroll
            for (int c = 0; c < 4; c++) acc[a][b][c] = 0.0f;

    uint32_t aBase = (uint32_t)(((wm * 32 + (lane & 15)) * GLDA + (lane >> 4) * 8) * 2);
    uint32_t bBase = (uint32_t)(((wn * 64 + (lane & 7) + ((lane >> 4) & 1) * 8) * GLDA
                                 + ((lane >> 3) & 1) * 8) * 2);

    load_chunk(0, 0);
    load_chunk(1, 1);
    for (int kc = 0; kc < GI_NC; kc++) {
        int st = kc % 3;
        if (kc == GI_NC - 1) { asm volatile("cp.async.wait_group 0;" ::: "memory"); }
        else                 { asm volatile("cp.async.wait_group 1;" ::: "memory"); }
        __syncthreads();
        if (kc + 2 < GI_NC) load_chunk(kc + 2, (kc + 2) % 3);
        uint32_t sa = sA + st * GBUF_B + aBase;
        uint32_t sbm = sB + st * GBUF_B + bBase;
        #pragma unroll
        for (int ks = 0; ks < 4; ks++) {
            uint32_t koff = (uint32_t)(ks * 16 * 2);
            uint32_t a0[4], a1[4];
            LDSM4(a0[0], a0[1], a0[2], a0[3], sa + koff);
            LDSM4(a1[0], a1[1], a1[2], a1[3], sa + 16 * GLDA * 2 + koff);
            uint32_t bf[16];
            #pragma unroll
            for (int nt = 0; nt < 4; nt++)
                LDSM4(bf[nt * 4 + 0], bf[nt * 4 + 1], bf[nt * 4 + 2], bf[nt * 4 + 3],
                      sbm + nt * 16 * GLDA * 2 + koff);
            #pragma unroll
            for (int j = 0; j < 8; j++) {
                int nt = j >> 1, hf = j & 1;
                MMA16816(acc[0][j], a0, bf[nt * 4 + hf * 2], bf[nt * 4 + hf * 2 + 1]);
                MMA16816(acc[1][j], a1, bf[nt * 4 + hf * 2], bf[nt * 4 + hf * 2 + 1]);
            }
        }
    }
    __syncthreads();

    #pragma unroll
    for (int mt = 0; mt < 2; mt++) {
        #pragma unroll
        for (int half = 0; half < 2; half++) {
            int m = m0 + wm * 32 + mt * 16 + (lane >> 2) + half * 8;
            int t = m >> 5, b = m & 31;
            float* obase = outg + (size_t)t * (H3 * BB) + b;
            #pragma unroll
            for (int j = 0; j < 8; j++) {
                int n = n0 + wn * 64 + j * 8 + (lane & 3) * 2;
                obase[(size_t)n * 32] = acc[mt][j][half * 2 + 0] + __ldg(bih + n);
                obase[(size_t)(n + 1) * 32] = acc[mt][j][half * 2 + 1] + __ldg(bih + n + 1);
            }
        }
    }
}

// ---------------- encoder scan (weights in SMEM, gi prefetched) ----------------
__global__ void __launch_bounds__(512) enc_scan(const float* __restrict__ Whh,
                                                const float* __restrict__ bhh) {
    int wid = threadIdx.x >> 5, lane = threadIdx.x & 31;
    int iLocal = wid & 3;
    int kq = wid >> 2;
    int i = blockIdx.x * 4 + iLocal;
    __shared__ float sW[16][3][128];
    __shared__ float ps[4][3][3][32];
    __shared__ float sgi[2][12][32];
    __shared__ float sbh[12];

    #pragma unroll
    for (int g = 0; g < 3; g++) {
        float4 w = *(const float4*)(Whh + ((size_t)g * HH + i) * HH + kq * 128 + lane * 4);
        *(float4*)&sW[wid][g][lane * 4] = w;
    }
    if (threadIdx.x < 12) {
        int g = threadIdx.x >> 2, il = threadIdx.x & 3;
        sbh[threadIdx.x] = bhh[g * HH + blockIdx.x * 4 + il];
    }

    auto prefetch_gi = [&](int t, int buf) {
        if (threadIdx.x < 96) {
            int row = threadIdx.x >> 3, u = threadIdx.x & 7;
            int g = row >> 2, il = row & 3;
            const float* src = g_enc_gi + (size_t)t * (H3 * BB)
                             + ((size_t)g * HH + blockIdx.x * 4 + il) * 32 + u * 4;
            cpasync16(smem_u32(&sgi[buf][row][u * 4]), src);
        }
        asm volatile("cp.async.commit_group;" ::: "memory");
    };
    prefetch_gi(0, 0);
    __syncthreads();

    for (int t = 0; t < SS; t++) {
        if (t + 1 < SS) prefetch_gi(t + 1, (t + 1) & 1);
        const float* hprev = t ? (g_eo + (t - 1) * (HH * BB)) : g_h0;
        const float* hp = hprev + kq * 128 * 32 + lane;
        float s0 = 0, s1 = 0, s2 = 0;
        #pragma unroll 8
        for (int q = 0; q < 32; q++) {
            float h0 = hp[q * 128 + 0];
            float h1 = hp[q * 128 + 32];
            float h2 = hp[q * 128 + 64];
            float h3 = hp[q * 128 + 96];
            float4 w0 = *(const float4*)&sW[wid][0][q * 4];
            float4 w1 = *(const float4*)&sW[wid][1][q * 4];
            float4 w2 = *(const float4*)&sW[wid][2][q * 4];
            s0 += w0.x * h0 + w0.y * h1 + w0.z * h2 + w0.w * h3;
            s1 += w1.x * h0 + w1.y * h1 + w1.z * h2 + w1.w * h3;
            s2 += w2.x * h0 + w2.y * h1 + w2.z * h2 + w2.w * h3;
        }
        if (kq > 0) {
            ps[iLocal][kq - 1][0][lane] = s0;
            ps[iLocal][kq - 1][1][lane] = s1;
            ps[iLocal][kq - 1][2][lane] = s2;
        }
        asm volatile("cp.async.wait_group 1;" ::: "memory");
        __syncthreads();
        if (wid < 4) {
            float rh = s0 + ps[wid][0][0][lane] + ps[wid][1][0][lane] + ps[wid][2][0][lane] + sbh[wid];
            float zh = s1 + ps[wid][0][1][lane] + ps[wid][1][1][lane] + ps[wid][2][1][lane] + sbh[4 + wid];
            float nh = s2 + ps[wid][0][2][lane] + ps[wid][1][2][lane] + ps[wid][2][2][lane] + sbh[8 + wid];
            float ir = sgi[t & 1][wid][lane];
            float iz = sgi[t & 1][4 + wid][lane];
            float in_ = sgi[t & 1][8 + wid][lane];
            float r = sigm(ir + rh);
            float z = sigm(iz + zh);
            float n = tanhf(in_ + r * nh);
            int ii = blockIdx.x * 4 + wid;
            float hv = hprev[ii * 32 + lane];
            g_eo[t * (HH * BB) + ii * 32 + lane] = (1.0f - z) * n + z * hv;
        }
        grid_sync(gridDim.x);
    }
}

// ---------------- decoder scan (phase-D weights in dynamic SMEM, gie prefetched)
__global__ void __launch_bounds__(512) dec_scan(const float* __restrict__ Whh,
                                                const float* __restrict__ bhh,
                                                const float* __restrict__ Wih,
                                                const int* __restrict__ src) {
    extern __shared__ float sWD[];
    int wid = threadIdx.x >> 5, lane = threadIdx.x & 31;
    int iLocal = wid & 3;
    int kqD = wid >> 2;
    int iD = blockIdx.x * 4 + iLocal;
    __shared__ float psA[2][8][32];
    __shared__ float psC[4][4][32];
    __shared__ float denS[32];
    __shared__ float psD[4][3][6][32];
    __shared__ float sgie[12][32];
    __shared__ float sbh[12];

    float* wrow = sWD + wid * 6 * 128;
    #pragma unroll
    for (int g = 0; g < 3; g++) {
        *(float4*)&wrow[g * 128 + lane * 4] =
            *(const float4*)(Whh + ((size_t)g * HH + iD) * HH + kqD * 128 + lane * 4);
        *(float4*)&wrow[(3 + g) * 128 + lane * 4] =
            *(const float4*)(Wih + ((size_t)g * HH + iD) * 768 + EE + kqD * 128 + lane * 4);
    }
    if (threadIdx.x < 12) {
        int g = threadIdx.x >> 2, il = threadIdx.x & 3;
        sbh[threadIdx.x] = bhh[g * HH + blockIdx.x * 4 + il];
    }
    __syncthreads();

    for (int t = 0; t < TT; t++) {
        if (threadIdx.x < 96) {
            int row = threadIdx.x >> 3, u = threadIdx.x & 7;
            int g = row >> 2, il = row & 3;
            const float* srcp = g_dec_gie + (size_t)t * (H3 * BB)
                              + ((size_t)g * HH + blockIdx.x * 4 + il) * 32 + u * 4;
            cpasync16(smem_u32(&sgie[row][u * 4]), srcp);
        }
        asm volatile("cp.async.commit_group;" ::: "memory");

        const float* h = t ? g_hdec[t & 1] : (g_eo + (SS - 1) * (HH * BB));
        {
            int s = blockIdx.x * 2 + (wid & 1);
            int kq8 = wid >> 1;
            float acc = 0.0f;
            const float* eo = g_eo + s * (HH * BB) + kq8 * 64 * 32 + lane;
            const float* hp = h + kq8 * 64 * 32 + lane;
            #pragma unroll 8
            for (int k = 0; k < 64; k++) acc += eo[k * 32] * hp[k * 32];
            psA[wid & 1][kq8][lane] = acc;
            __syncthreads();
            if (wid < 2) {
                int ss2 = blockIdx.x * 2 + wid;
                float sc = 0.0f;
                #pragma unroll
                for (int q = 0; q < 8; q++) sc += psA[wid][q][lane];
                int tokv = src[lane * SS + ss2];
                float e = (tokv == 0) ? 0.0f : __expf(sc);
                g_scores[ss2 * 32 + lane] = e;
            }
        }
        grid_sync(gridDim.x);
        {
            int k = blockIdx.x * 4 + (wid & 3);
            int sq = wid >> 2;
            float acc = 0.0f;
            const float* eo = g_eo + sq * 64 * (HH * BB) + k * 32 + lane;
            const float* sce = g_scores + sq * 64 * 32 + lane;
            #pragma unroll 8
            for (int s = 0; s < 64; s++) acc += sce[s * 32] * eo[s * (HH * BB)];
            psC[wid & 3][sq][lane] = acc;
            if (wid == 0) {
                float d = 0.0f;
                const float* sp = g_scores + lane;
                #pragma unroll 8
                for (int s = 0; s < SS; s++) d += sp[s * 32];
                denS[lane] = d;
            }
            __syncthreads();
            if (wid < 4) {
                int kk = blockIdx.x * 4 + wid;
                float c = (psC[wid][0][lane] + psC[wid][1][lane] + psC[wid][2][lane] + psC[wid][3][lane])
                          / denS[lane];
                g_ctx[kk * 32 + lane] = c;
                g_pred[(t * 32 + lane) * (2 * HH) + HH + kk] = c;
            }
        }
        grid_sync(gridDim.x);
        {
            float a0 = 0, a1 = 0, a2 = 0, c0 = 0, c1 = 0, c2 = 0;
            {
                const float* hp = h + kqD * 128 * 32 + lane;
                const float* cp = g_ctx + kqD * 128 * 32 + lane;
                #pragma unroll 4
                for (int q = 0; q < 32; q++) {
                    float h0 = hp[q * 128 + 0], h1 = hp[q * 128 + 32];
                    float h2 = hp[q * 128 + 64], h3 = hp[q * 128 + 96];
                    float x0 = cp[q * 128 + 0], x1 = cp[q * 128 + 32];
                    float x2 = cp[q * 128 + 64], x3 = cp[q * 128 + 96];
                    float4 w;
                    w = *(const float4*)&wrow[0 * 128 + q * 4];
                    a0 += w.x * h0 + w.y * h1 + w.z * h2 + w.w * h3;
                    w = *(const float4*)&wrow[1 * 128 + q * 4];
                    a1 += w.x * h0 + w.y * h1 + w.z * h2 + w.w * h3;
                    w = *(const float4*)&wrow[2 * 128 + q * 4];
                    a2 += w.x * h0 + w.y * h1 + w.z * h2 + w.w * h3;
                    w = *(const float4*)&wrow[3 * 128 + q * 4];
                    c0 += w.x * x0 + w.y * x1 + w.z * x2 + w.w * x3;
                    w = *(const float4*)&wrow[4 * 128 + q * 4];
                    c1 += w.x * x0 + w.y * x1 + w.z * x2 + w.w * x3;
                    w = *(const float4*)&wrow[5 * 128 + q * 4];
                    c2 += w.x * x0 + w.y * x1 + w.z * x2 + w.w * x3;
                }
            }
            if (kqD > 0) {
                psD[iLocal][kqD - 1][0][lane] = a0;
                psD[iLocal][kqD - 1][1][lane] = a1;
                psD[iLocal][kqD - 1][2][lane] = a2;
                psD[iLocal][kqD - 1][3][lane] = c0;
                psD[iLocal][kqD - 1][4][lane] = c1;
                psD[iLocal][kqD - 1][5][lane] = c2;
            }
            asm volatile("cp.async.wait_group 0;" ::: "memory");
            __syncthreads();
            if (wid < 4) {
                float rh = a0, zh = a1, nh = a2, rc = c0, zc = c1, nc = c2;
                #pragma unroll
                for (int kk = 0; kk < 3; kk++) {
                    rh += psD[wid][kk][0][lane];
                    zh += psD[wid][kk][1][lane];
                    nh += psD[wid][kk][2][lane];
                    rc += psD[wid][kk][3][lane];
                    zc += psD[wid][kk][4][lane];
                    nc += psD[wid][kk][5][lane];
                }
                rh += sbh[wid]; zh += sbh[4 + wid]; nh += sbh[8 + wid];
                float ir = sgie[wid][lane] + rc;
                float iz = sgie[4 + wid][lane] + zc;
                float in_ = sgie[8 + wid][lane] + nc;
                float r = sigm(ir + rh);
                float z = sigm(iz + zh);
                float n = tanhf(in_ + r * nh);
                int ii = blockIdx.x * 4 + wid;
                float hold = h[ii * 32 + lane];
                float hn = (1.0f - z) * n + z * hold;
                g_hdec[(t + 1) & 1][ii * 32 + lane] = hn;
                g_pred[(t * 32 + lane) * (2 * HH) + ii] = hn;
            }
        }
        grid_sync(gridDim.x);
    }
}

// ---------------- fc GEMM via mma.sync fp16 (256 thr, 128x128, 2 segments)
__global__ void __launch_bounds__(256) fc_mma(const float* __restrict__ bias,
                                              float* __restrict__ out) {
    extern __shared__ uint8_t dynsmem[];
    uint32_t sA = smem_u32(dynsmem);           // 3 stages
    uint32_t sB = sA + 3 * GBUF_B;

    int tid = threadIdx.x;
    int wid = tid >> 5, lane = tid & 31;
    int wm = wid & 3, wn = wid >> 2;
    int m0 = blockIdx.x * GBM;
    int n0 = blockIdx.y * GBN;

    const char* Ag = (const char*)(g_Ab + (size_t)m0 * FCKA);
    const char* Bg = (const char*)(g_Wb + (size_t)n0 * FCKB);
    int lrow = tid >> 3, lu = tid & 7;

    auto load_chunk = [&](int kc, int st) {
        int seg = kc >> 4, c = kc & 15;
        size_t aoff = (size_t)(c * 64) * 2;                       // A always hi
        size_t boff = (size_t)((seg ? 1024 : 0) + c * 64) * 2;    // B hi or lo
        uint32_t sa = sA + st * GBUF_B;
        uint32_t sbm = sB + st * GBUF_B;
        #pragma unroll
        for (int it = 0; it < 4; it++) {
            int row = it * 32 + lrow;
            uint32_t doff = (uint32_t)(row * (GLDA * 2) + lu * 16);
            cpasync16(sa + doff, Ag + (size_t)row * (FCKA * 2) + aoff + lu * 16);
            cpasync16(sbm + doff, Bg + (size_t)row * (FCKB * 2) + boff + lu * 16);
        }
        asm volatile("cp.async.commit_group;" ::: "memory");
    };

    float acc[2][8][4];
    #pragma unroll
    for (int a = 0; a < 2; a++)
        #pragma unroll
        for (int b = 0; b < 8; b++)
            #pragma unroll
            for (int c = 0; c < 4; c++) acc[a][b][c] = 0.0f;

    uint32_t aBase = (uint32_t)(((wm * 32 + (lane & 15)) * GLDA + (lane >> 4) * 8) * 2);
    uint32_t bBase = (uint32_t)(((wn * 64 + (lane & 7) + ((lane >> 4) & 1) * 8) * GLDA
                                 + ((lane >> 3) & 1) * 8) * 2);

    load_chunk(0, 0);
    load_chunk(1, 1);
    for (int kc = 0; kc < FC_NC; kc++) {
        int st = kc % 3;
        if (kc == FC_NC - 1) { asm volatile("cp.async.wait_group 0;" ::: "memory"); }
        else                 { asm volatile("cp.async.wait_group 1;" ::: "memory"); }
        __syncthreads();
        if (kc + 2 < FC_NC) load_chunk(kc + 2, (kc + 2) % 3);
        uint32_t sa = sA + st * GBUF_B + aBase;
        uint32_t sbm = sB + st * GBUF_B + bBase;
        #pragma unroll
        for (int ks = 0; ks < 4; ks++) {
            uint32_t koff = (uint32_t)(ks * 16 * 2);
            uint32_t a0[4], a1[4];
            LDSM4(a0[0], a0[1], a0[2], a0[3], sa + koff);
            LDSM4(a1[0], a1[1], a1[2], a1[3], sa + 16 * GLDA * 2 + koff);
            uint32_t bf[16];
            #pragma unroll
            for (int nt = 0; nt < 4; nt++)
                LDSM4(bf[nt * 4 + 0], bf[nt * 4 + 1], bf[nt * 4 + 2], bf[nt * 4 + 3],
                      sbm + nt * 16 * GLDA * 2 + koff);
            #pragma unroll
            for (int j = 0; j < 8; j++) {
                int nt = j >> 1, hf = j & 1;
                MMA16816H(acc[0][j], a0, bf[nt * 4 + hf * 2], bf[nt * 4 + hf * 2 + 1]);
                MMA16816H(acc[1][j], a1, bf[nt * 4 + hf * 2], bf[nt * 4 + hf * 2 + 1]);
            }
        }
    }
    __syncthreads();

    float bv[8][2];
    #pragma unroll
    for (int j = 0; j < 8; j++) {
        int n = n0 + wn * 64 + j * 8 + (lane & 3) * 2;
        bv[j][0] = __ldg(bias + n);
        bv[j][1] = __ldg(bias + n + 1);
    }
    #pragma unroll
    for (int mt = 0; mt < 2; mt++) {
        #pragma unroll
        for (int half = 0; half < 2; half++) {
            int m = m0 + wm * 32 + mt * 16 + (lane >> 2) + half * 8;
            int t = m >> 5, b = m & 31;
            float* orow = out + (size_t)b * (TT * VV) + (size_t)t * VV;
            #pragma unroll
            for (int j = 0; j < 8; j++) {
                int n = n0 + wn * 64 + j * 8 + (lane & 3) * 2;
                float2 v;
                v.x = acc[mt][j][half * 2 + 0] + bv[j][0];
                v.y = acc[mt][j][half * 2 + 1] + bv[j][1];
                *(float2*)(orow + n) = v;
            }
        }
    }
}

// ---------------- launch (serial, proven order) ----------------
extern "C" void kernel_launch(void* const* d_in, const int* in_sizes, int n_in,
                              void* d_out, int out_size) {
    const int* src = (const int*)d_in[0];
    const int* tgt = (const int*)d_in[2];
    const float* enc_emb = (const float*)d_in[3];
    const float* enc_Wih = (const float*)d_in[4];
    const float* enc_Whh = (const float*)d_in[5];
    const float* enc_bih = (const float*)d_in[6];
    const float* enc_bhh = (const float*)d_in[7];
    const float* dec_emb = (const float*)d_in[8];
    const float* dec_Wih = (const float*)d_in[9];
    const float* dec_Whh = (const float*)d_in[10];
    const float* dec_bih = (const float*)d_in[11];
    const float* dec_bhh = (const float*)d_in[12];
    const float* fc_W = (const float*)d_in[13];
    const float* fc_b = (const float*)d_in[14];
    float* out = (float*)d_out;

    cudaFuncSetAttribute(fc_mma, cudaFuncAttributeMaxDynamicSharedMemorySize, MM_SMEM);
    cudaFuncSetAttribute(gi_mma, cudaFuncAttributeMaxDynamicSharedMemorySize, MM_SMEM);
    cudaFuncSetAttribute(dec_scan, cudaFuncAttributeMaxDynamicSharedMemorySize, DEC_WSMEM);

    gatherX<<<SS * BB / 8, 256>>>(enc_emb, src, SS, 0);
    splitWih<<<H3 / 8, 256>>>(enc_Wih, EE, 0);
    gi_mma<<<dim3(SS * BB / GBM, H3 / GBN), 256, MM_SMEM>>>(enc_bih, 0);
    enc_scan<<<NCTA, 512>>>(enc_Whh, enc_bhh);
    gatherX<<<TT * BB / 8, 256>>>(dec_emb, tgt, TT, 1);
    splitWih<<<H3 / 8, 256>>>(dec_Wih, EE + HH, 1);
    gi_mma<<<dim3(TT * BB / GBM, H3 / GBN), 256, MM_SMEM>>>(dec_bih, 1);
    dec_scan<<<NCTA, 512, DEC_WSMEM>>>(dec_Whh, dec_bhh, dec_Wih, src);
    convA<<<512, 1024>>>();
    convW<<<(VV * 256) / 1024, 1024>>>(fc_W);
    fc_mma<<<dim3(TT * BB / GBM, VV / GBN), 256, MM_SMEM>>>(fc_b, out);
}